// round 11
// baseline (speedup 1.0000x reference)
#include <cuda_runtime.h>
#include <cuda_bf16.h>
#include <math.h>
#include <stdint.h>

#define CB 2
#define CS 2048
#define CD 2048
#define CH 16
#define CHD 128
#define CM (CB*CS)          // 4096 rows total
#define SCALE 0.08838834764831845f   // 1/sqrt(128)

// ---------------------------------------------------------------------------
// Scratch (allocation-free rule: static device globals)
// ---------------------------------------------------------------------------
__device__ float g_q[(size_t)CM * CD];
__device__ float g_k[(size_t)CM * CD];
__device__ float g_invf[64];

__device__ __nv_bfloat16 g_xh[(size_t)CM * CD];
__device__ __nv_bfloat16 g_xl[(size_t)CM * CD];
__device__ __nv_bfloat16 g_wqh[(size_t)CD * CD];
__device__ __nv_bfloat16 g_wql[(size_t)CD * CD];
__device__ __nv_bfloat16 g_wkh[(size_t)CD * CD];
__device__ __nv_bfloat16 g_wkl[(size_t)CD * CD];
__device__ __nv_bfloat16 g_wvh[(size_t)CD * CD];
__device__ __nv_bfloat16 g_wvl[(size_t)CD * CD];
__device__ __nv_bfloat16 g_woh[(size_t)CD * CD];
__device__ __nv_bfloat16 g_wol[(size_t)CD * CD];
__device__ __nv_bfloat16 g_aoh[(size_t)CM * CD];
__device__ __nv_bfloat16 g_aol[(size_t)CM * CD];

// bf16 hi/lo planes for attention inputs
__device__ __nv_bfloat16 g_qh[(size_t)CM * CD];
__device__ __nv_bfloat16 g_ql[(size_t)CM * CD];
__device__ __nv_bfloat16 g_kh[(size_t)CM * CD];
__device__ __nv_bfloat16 g_kl[(size_t)CM * CD];
__device__ __nv_bfloat16 g_vh[(size_t)CM * CD];
__device__ __nv_bfloat16 g_vl[(size_t)CM * CD];

// ---------------------------------------------------------------------------
// PTX helpers
// ---------------------------------------------------------------------------
__device__ __forceinline__ uint32_t smem_u32(const void* p) {
    return (uint32_t)__cvta_generic_to_shared(p);
}

__device__ __forceinline__ void ldsm4(uint32_t& r0, uint32_t& r1,
                                      uint32_t& r2, uint32_t& r3, uint32_t addr) {
    asm volatile("ldmatrix.sync.aligned.m8n8.x4.shared.b16 {%0,%1,%2,%3}, [%4];"
                 : "=r"(r0), "=r"(r1), "=r"(r2), "=r"(r3) : "r"(addr));
}

__device__ __forceinline__ void ldsm4t(uint32_t& r0, uint32_t& r1,
                                       uint32_t& r2, uint32_t& r3, uint32_t addr) {
    asm volatile("ldmatrix.sync.aligned.m8n8.x4.trans.shared.b16 {%0,%1,%2,%3}, [%4];"
                 : "=r"(r0), "=r"(r1), "=r"(r2), "=r"(r3) : "r"(addr));
}

__device__ __forceinline__ void mma16816(float* c, const uint32_t* a, const uint32_t* b) {
    asm volatile(
        "mma.sync.aligned.m16n8k16.row.col.f32.bf16.bf16.f32 "
        "{%0,%1,%2,%3}, {%4,%5,%6,%7}, {%8,%9}, {%0,%1,%2,%3};"
        : "+f"(c[0]), "+f"(c[1]), "+f"(c[2]), "+f"(c[3])
        : "r"(a[0]), "r"(a[1]), "r"(a[2]), "r"(a[3]), "r"(b[0]), "r"(b[1]));
}

__device__ __forceinline__ void cp16(uint32_t saddr, const void* gaddr) {
    asm volatile("cp.async.cg.shared.global [%0], [%1], 16;"
                 :: "r"(saddr), "l"(gaddr) : "memory");
}
__device__ __forceinline__ void cp_commit() {
    asm volatile("cp.async.commit_group;" ::: "memory");
}
template <int N>
__device__ __forceinline__ void cp_wait() {
    asm volatile("cp.async.wait_group %0;" :: "n"(N) : "memory");
}

// ---------------------------------------------------------------------------
__global__ void init_invf()
{
    int i = threadIdx.x;
    if (i < 64)
        g_invf[i] = (float)(1.0 / pow(10000.0, (double)(2 * i) / (double)CHD));
}

// ---------------------------------------------------------------------------
// fp32 -> (bf16 hi, bf16 lo) split conversion. 4 elements per thread.
// blockIdx.y selects among up to 4 (src, hi, lo) triples.
// ---------------------------------------------------------------------------
__global__ __launch_bounds__(256) void convert_hilo(
    const float* __restrict__ s0, __nv_bfloat16* __restrict__ h0d, __nv_bfloat16* __restrict__ l0d,
    const float* __restrict__ s1, __nv_bfloat16* __restrict__ h1d, __nv_bfloat16* __restrict__ l1d,
    const float* __restrict__ s2, __nv_bfloat16* __restrict__ h2d, __nv_bfloat16* __restrict__ l2d,
    const float* __restrict__ s3, __nv_bfloat16* __restrict__ h3d, __nv_bfloat16* __restrict__ l3d,
    int n4)
{
    const float* src = (blockIdx.y == 0) ? s0 : (blockIdx.y == 1) ? s1 :
                       (blockIdx.y == 2) ? s2 : s3;
    __nv_bfloat16* hi = (blockIdx.y == 0) ? h0d : (blockIdx.y == 1) ? h1d :
                        (blockIdx.y == 2) ? h2d : h3d;
    __nv_bfloat16* lo = (blockIdx.y == 0) ? l0d : (blockIdx.y == 1) ? l1d :
                        (blockIdx.y == 2) ? l2d : l3d;

    int i = blockIdx.x * 256 + threadIdx.x;
    if (i >= n4) return;
    float4 v = ((const float4*)src)[i];
    __nv_bfloat16 h0 = __float2bfloat16_rn(v.x);
    __nv_bfloat16 h1 = __float2bfloat16_rn(v.y);
    __nv_bfloat16 h2 = __float2bfloat16_rn(v.z);
    __nv_bfloat16 h3 = __float2bfloat16_rn(v.w);
    __nv_bfloat16 l0 = __float2bfloat16_rn(v.x - __bfloat162float(h0));
    __nv_bfloat16 l1 = __float2bfloat16_rn(v.y - __bfloat162float(h1));
    __nv_bfloat16 l2 = __float2bfloat16_rn(v.z - __bfloat162float(h2));
    __nv_bfloat16 l3 = __float2bfloat16_rn(v.w - __bfloat162float(h3));
    ((__nv_bfloat162*)hi)[2 * i]     = __nv_bfloat162(h0, h1);
    ((__nv_bfloat162*)hi)[2 * i + 1] = __nv_bfloat162(h2, h3);
    ((__nv_bfloat162*)lo)[2 * i]     = __nv_bfloat162(l0, l1);
    ((__nv_bfloat162*)lo)[2 * i + 1] = __nv_bfloat162(l2, l3);
}

// ---------------------------------------------------------------------------
// bf16-split tensor-core NT GEMM, 64x64 warp tiles, 2 CTAs/SM.
// C = Ah Bh^T + Ah Bl^T + Al Bh^T   (fp32 accumulate)
// CTA tile 128x128x32, 128 threads = 4 warps (2x2), warp tile 64x64.
// cp.async double buffer, single sync per k-step.
// smem rows: 40 bf16 (80B stride) -> conflict-free ldmatrix phases.
// blockIdx.z selects among up to 3 (B, C) pairs; z == zbf writes bf16 hi/lo.
// ---------------------------------------------------------------------------
#define GAPLANE 10240                // bytes per A plane (128 rows x 80B)
#define GBPLANE 10240                // bytes per B plane (128 rows x 80B)
#define GSTAGE  40960                // Ah, Al, Bh, Bl
#define GEMM_SMEM (2 * GSTAGE)       // 81920 B; x2 CTAs = 160KB/SM

__global__ __launch_bounds__(128, 2) void gemm_bf16x3(
    const __nv_bfloat16* __restrict__ Ah, const __nv_bfloat16* __restrict__ Al,
    const __nv_bfloat16* __restrict__ Bh0, const __nv_bfloat16* __restrict__ Bl0,
    const __nv_bfloat16* __restrict__ Bh1, const __nv_bfloat16* __restrict__ Bl1,
    const __nv_bfloat16* __restrict__ Bh2, const __nv_bfloat16* __restrict__ Bl2,
    float* __restrict__ C0, float* __restrict__ C1,
    __nv_bfloat16* __restrict__ Cbh, __nv_bfloat16* __restrict__ Cbl, int zbf,
    int N, int K)
{
    extern __shared__ char smg[];
    const uint32_t sb = smem_u32(smg);

    const __nv_bfloat16* Bh = (blockIdx.z == 0) ? Bh0 : (blockIdx.z == 1) ? Bh1 : Bh2;
    const __nv_bfloat16* Bl = (blockIdx.z == 0) ? Bl0 : (blockIdx.z == 1) ? Bl1 : Bl2;
    float*               C  = (blockIdx.z == 0) ? C0  : C1;

    const int tid  = threadIdx.x;
    const int lane = tid & 31;
    const int wid  = tid >> 5;
    const int wm   = wid >> 1;      // 0..1
    const int wn   = wid & 1;       // 0..1
    const int bm   = blockIdx.y << 7;
    const int bn   = blockIdx.x << 7;

    float acc[4][8][4];
#pragma unroll
    for (int i = 0; i < 4; i++)
#pragma unroll
        for (int j = 0; j < 8; j++)
#pragma unroll
            for (int r = 0; r < 4; r++) acc[i][j][r] = 0.f;

    // ldmatrix lane-address components
    const int a_row  = wm * 64 + (lane & 15);
    const int a_ch   = lane >> 4;
    const int b_rowb = wn * 64 + (lane & 7) + ((lane >> 4) << 3);
    const int b_ch   = (lane >> 3) & 1;

    const int iters = K >> 5;

    // issue k-chunk ki into buffer ki&1 (16 cp16 per thread)
    auto issue = [&](int ki) {
        const uint32_t sa = sb + (ki & 1) * GSTAGE;
        const int k0 = ki << 5;
#pragma unroll
        for (int p = 0; p < 4; p++) {
            const int j   = tid + (p << 7);
            const int row = j >> 2, c = j & 3;
            const uint32_t so = row * 80 + c * 16;
            const size_t gA = (size_t)(bm + row) * K + k0 + c * 8;
            const size_t gB = (size_t)(bn + row) * K + k0 + c * 8;
            cp16(sa + so,                        Ah + gA);
            cp16(sa + GAPLANE + so,              Al + gA);
            cp16(sa + 2 * GAPLANE + so,          Bh + gB);
            cp16(sa + 2 * GAPLANE + GBPLANE + so, Bl + gB);
        }
        cp_commit();
    };

    issue(0);

    for (int it = 0; it < iters; it++) {
        cp_wait<0>();          // stage it resident
        __syncthreads();       // all warps done reading buffer (it+1)&1 (MMA it-1)

        if (it + 1 < iters) issue(it + 1);

        const uint32_t stage = sb + (it & 1) * GSTAGE;
        const uint32_t stB   = stage + 2 * GAPLANE;

#pragma unroll
        for (int kh = 0; kh < 2; kh++) {
            uint32_t ah[4][4], al[4][4];
#pragma unroll
            for (int mt = 0; mt < 4; mt++) {
                uint32_t addr = stage + (a_row + mt * 16) * 80 + (2 * kh + a_ch) * 16;
                ldsm4(ah[mt][0], ah[mt][1], ah[mt][2], ah[mt][3], addr);
                ldsm4(al[mt][0], al[mt][1], al[mt][2], al[mt][3], addr + GAPLANE);
            }
#pragma unroll
            for (int hp = 0; hp < 2; hp++) {
                uint32_t bh[4][2], bl[4][2];
#pragma unroll
                for (int nt = 0; nt < 2; nt++) {
                    uint32_t addr = stB + (b_rowb + (hp * 2 + nt) * 16) * 80 +
                                    (2 * kh + b_ch) * 16;
                    ldsm4(bh[nt * 2][0], bh[nt * 2][1],
                          bh[nt * 2 + 1][0], bh[nt * 2 + 1][1], addr);
                    ldsm4(bl[nt * 2][0], bl[nt * 2][1],
                          bl[nt * 2 + 1][0], bl[nt * 2 + 1][1], addr + GBPLANE);
                }
#pragma unroll
                for (int mt = 0; mt < 4; mt++)
#pragma unroll
                    for (int j = 0; j < 4; j++) {
                        mma16816(acc[mt][hp * 4 + j], ah[mt], bh[j]);
                        mma16816(acc[mt][hp * 4 + j], ah[mt], bl[j]);
                        mma16816(acc[mt][hp * 4 + j], al[mt], bh[j]);
                    }
            }
        }
    }

    if ((int)blockIdx.z == zbf) {
#pragma unroll
        for (int mt = 0; mt < 4; mt++) {
            const int gm = bm + wm * 64 + mt * 16 + (lane >> 2);
#pragma unroll
            for (int n8 = 0; n8 < 8; n8++) {
                const int gc = bn + wn * 64 + n8 * 8 + ((lane & 3) << 1);
#pragma unroll
                for (int hrow = 0; hrow < 2; hrow++) {
                    float o0 = acc[mt][n8][hrow * 2];
                    float o1 = acc[mt][n8][hrow * 2 + 1];
                    size_t off = (size_t)(gm + hrow * 8) * N + gc;
                    __nv_bfloat16 h0 = __float2bfloat16_rn(o0);
                    __nv_bfloat16 h1 = __float2bfloat16_rn(o1);
                    __nv_bfloat162 hv(h0, h1);
                    __nv_bfloat162 lv(__float2bfloat16_rn(o0 - __bfloat162float(h0)),
                                      __float2bfloat16_rn(o1 - __bfloat162float(h1)));
                    *(uint32_t*)(&Cbh[off]) = *(uint32_t*)&hv;
                    *(uint32_t*)(&Cbl[off]) = *(uint32_t*)&lv;
                }
            }
        }
    } else {
#pragma unroll
        for (int mt = 0; mt < 4; mt++) {
            const int gm = bm + wm * 64 + mt * 16 + (lane >> 2);
#pragma unroll
            for (int n8 = 0; n8 < 8; n8++) {
                const int gc = bn + wn * 64 + n8 * 8 + ((lane & 3) << 1);
                *(float2*)(&C[(size_t)gm * N + gc]) =
                    make_float2(acc[mt][n8][0], acc[mt][n8][1]);
                *(float2*)(&C[(size_t)(gm + 8) * N + gc]) =
                    make_float2(acc[mt][n8][2], acc[mt][n8][3]);
            }
        }
    }
}

// ---------------------------------------------------------------------------
// RoPE: reads fp32 g_q/g_k, writes bf16 hi/lo planes qh/ql/kh/kl.
// ---------------------------------------------------------------------------
__global__ __launch_bounds__(256) void rope_split()
{
    int idx = blockIdx.x * 256 + threadIdx.x;
    int i = idx & 63;
    int m = idx >> 10;
    int s = m & (CS - 1);

    float inv = g_invf[i];
    float ang = (float)s * inv;
    float c, sn;
    sincosf(ang, &sn, &c);

    int h = (idx >> 6) & (CH - 1);
    size_t base = (size_t)m * CD + (size_t)h * CHD;

    float q1 = g_q[base + i], q2 = g_q[base + i + 64];
    float rq1 = q1 * c - q2 * sn;
    float rq2 = q2 * c + q1 * sn;
    float k1 = g_k[base + i], k2 = g_k[base + i + 64];
    float rk1 = k1 * c - k2 * sn;
    float rk2 = k2 * c + k1 * sn;

    __nv_bfloat16 h1 = __float2bfloat16_rn(rq1);
    __nv_bfloat16 h2 = __float2bfloat16_rn(rq2);
    g_qh[base + i]      = h1;
    g_qh[base + i + 64] = h2;
    g_ql[base + i]      = __float2bfloat16_rn(rq1 - __bfloat162float(h1));
    g_ql[base + i + 64] = __float2bfloat16_rn(rq2 - __bfloat162float(h2));

    __nv_bfloat16 h3 = __float2bfloat16_rn(rk1);
    __nv_bfloat16 h4 = __float2bfloat16_rn(rk2);
    g_kh[base + i]      = h3;
    g_kh[base + i + 64] = h4;
    g_kl[base + i]      = __float2bfloat16_rn(rk1 - __bfloat162float(h3));
    g_kl[base + i + 64] = __float2bfloat16_rn(rk2 - __bfloat162float(h4));
}

// ---------------------------------------------------------------------------
// Tensor-core flash attention, pipelined 64-col k-tiles (round-10 proven).
// ---------------------------------------------------------------------------
#define FOFF_QH  0
#define FOFF_QL  34816
#define FOFF_KV  69632
#define KVSLOT   34816          // 64 rows x 272B x 2 planes (h @0, l @17408)
#define FOFF_S   174080         // 128 rows x 272B
#define FOFF_ST  208896
#define FLASH_SMEM 210432

__global__ __launch_bounds__(256, 1) void flash_mma(const float* __restrict__ mask)
{
    extern __shared__ char smc[];
    float* m_s  = (float*)(smc + FOFF_ST);
    float* l_s  = m_s + 128;
    float* al_s = l_s + 128;

    const int tid  = threadIdx.x;
    const int lane = tid & 31;
    const int wid  = tid >> 5;
    const int wm   = wid >> 2;      // 0..1
    const int wn   = wid & 3;       // 0..3
    const int b    = blockIdx.z;
    const int h    = blockIdx.y;
    const int q0   = blockIdx.x << 7;

    const __nv_bfloat16* Qhg = g_qh + (size_t)(b * CS + q0) * CD + (size_t)h * CHD;
    const __nv_bfloat16* Qlg = g_ql + (size_t)(b * CS + q0) * CD + (size_t)h * CHD;
    const __nv_bfloat16* Khg = g_kh + (size_t)(b * CS) * CD + (size_t)h * CHD;
    const __nv_bfloat16* Klg = g_kl + (size_t)(b * CS) * CD + (size_t)h * CHD;
    const __nv_bfloat16* Vhg = g_vh + (size_t)(b * CS) * CD + (size_t)h * CHD;
    const __nv_bfloat16* Vlg = g_vl + (size_t)(b * CS) * CD + (size_t)h * CHD;

    const uint32_t sQ_u  = smem_u32(smc) + FOFF_QH;
    const uint32_t sKV_u = smem_u32(smc) + FOFF_KV;
    const uint32_t sS_u  = smem_u32(smc) + FOFF_S;

    // issue helpers: 64-row tile, 2 planes, 8 cp16/thread; always commit
    auto issueK = [&](int t) {
        if (t < 32) {
            const uint32_t buf = sKV_u + ((2 * t) % 3) * KVSLOT;
            const int k0 = t << 6;
            for (int i = tid; i < 1024; i += 256) {
                int r = i >> 4, c = i & 15;
                cp16(buf + r * 272 + c * 16,
                     Khg + (size_t)(k0 + r) * CD + c * 8);
                cp16(buf + 17408 + r * 272 + c * 16,
                     Klg + (size_t)(k0 + r) * CD + c * 8);
            }
        }
        cp_commit();
    };
    auto issueV = [&](int t) {
        if (t < 32) {
            const uint32_t buf = sKV_u + ((2 * t + 1) % 3) * KVSLOT;
            const int k0 = t << 6;
            for (int i = tid; i < 1024; i += 256) {
                int r = i >> 4, c = i & 15;
                cp16(buf + r * 272 + c * 16,
                     Vhg + (size_t)(k0 + r) * CD + c * 8);
                cp16(buf + 17408 + r * 272 + c * 16,
                     Vlg + (size_t)(k0 + r) * CD + c * 8);
            }
        }
        cp_commit();
    };

    // prologue: Q, K0, V0
    for (int i = tid; i < 2048; i += 256) {
        int r = i >> 4, c = i & 15;
        cp16(sQ_u + r * 272 + c * 16,         Qhg + (size_t)r * CD + c * 8);
        cp16(sQ_u + 34816 + r * 272 + c * 16, Qlg + (size_t)r * CD + c * 8);
    }
    cp_commit();
    issueK(0);
    issueV(0);
    if (tid < 128) { m_s[tid] = -INFINITY; l_s[tid] = 0.f; }

    float oacc[4][4][4];
#pragma unroll
    for (int i = 0; i < 4; i++)
#pragma unroll
        for (int j = 0; j < 4; j++)
#pragma unroll
            for (int r = 0; r < 4; r++) oacc[i][j][r] = 0.f;

    // lane address components (validated round-4 mappings)
    const int a_r = wm * 64 + (lane & 15);                 // + mt*16
    const int a_c = lane >> 4;                             // chunk parity
    const int b_r = wn * 16 + (lane & 7) + ((lane >> 4) << 3);
    const int b_c = (lane >> 3) & 1;
    const int v_key = ((lane >> 3) & 1) * 8 + (lane & 7);  // + t2*16
    const int v_dd  = wn * 32 + ((lane >> 4) << 3);        // + jj*16

    for (int t = 0; t < 32; t++) {
        const int k0 = t << 6;
        // a. K(t) resident; all warps past PV(t-1)
        cp_wait<1>();
        __syncthreads();

        // b. prefetch K(t+1) into V(t-1)'s slot (consumed + sync'd)
        issueK(t + 1);

        const uint32_t kbuf = sKV_u + ((2 * t) % 3) * KVSLOT;
        const uint32_t vbuf = sKV_u + ((2 * t + 1) % 3) * KVSLOT;

        // c. S = Q K^T (bf16x3), 64 cols
        float sacc[4][2][4];
#pragma unroll
        for (int i = 0; i < 4; i++)
#pragma unroll
            for (int j = 0; j < 2; j++)
#pragma unroll
                for (int r = 0; r < 4; r++) sacc[i][j][r] = 0.f;

#pragma unroll
        for (int tt = 0; tt < 8; tt++) {
            uint32_t ah[4][4], al[4][4], bh[2][2], bl[2][2];
#pragma unroll
            for (int mt = 0; mt < 4; mt++) {
                uint32_t addr = sQ_u + (a_r + mt * 16) * 272 + (tt * 2 + a_c) * 16;
                ldsm4(ah[mt][0], ah[mt][1], ah[mt][2], ah[mt][3], addr);
                ldsm4(al[mt][0], al[mt][1], al[mt][2], al[mt][3], addr + 34816);
            }
            {
                uint32_t addr = kbuf + b_r * 272 + (tt * 2 + b_c) * 16;
                ldsm4(bh[0][0], bh[0][1], bh[1][0], bh[1][1], addr);
                ldsm4(bl[0][0], bl[0][1], bl[1][0], bl[1][1], addr + 17408);
            }
#pragma unroll
            for (int mt = 0; mt < 4; mt++)
#pragma unroll
                for (int j = 0; j < 2; j++) {
                    mma16816(sacc[mt][j], ah[mt], bh[j]);
                    mma16816(sacc[mt][j], ah[mt], bl[j]);
                    mma16816(sacc[mt][j], al[mt], bh[j]);
                }
        }

        // store S fp32 (row stride 272B = 68 floats)
#pragma unroll
        for (int mt = 0; mt < 4; mt++) {
            const int r1 = wm * 64 + mt * 16 + (lane >> 2);
#pragma unroll
            for (int j = 0; j < 2; j++) {
                const int cc = wn * 16 + j * 8 + ((lane & 3) << 1);
                *(float2*)((float*)(smc + FOFF_S) + r1 * 68 + cc) =
                    make_float2(sacc[mt][j][0], sacc[mt][j][1]);
                *(float2*)((float*)(smc + FOFF_S) + (r1 + 8) * 68 + cc) =
                    make_float2(sacc[mt][j][2], sacc[mt][j][3]);
            }
        }
        // d. S complete; K(t) reads done
        __syncthreads();

        // e. prefetch V(t+1) into K(t)'s slot
        issueV(t + 1);

        // f. online softmax (2 threads/row, 32 cols each); P bf16 planes in place
        {
            const int r  = tid >> 1;
            const int hf = tid & 1;
            const float* mrow = mask + ((size_t)b * CS + (q0 + r)) * CS + k0 + hf * 32;
            const float* srow = (float*)(smc + FOFF_S + r * 272) + hf * 32;
            float v[32];
            float mprev = m_s[r];
            float lprev = l_s[r];

            float mx = -INFINITY;
#pragma unroll
            for (int c4 = 0; c4 < 8; c4++) {
                float4 sv = *(const float4*)(srow + c4 * 4);
                float4 mv = *(const float4*)(mrow + c4 * 4);
                v[c4*4+0] = sv.x * SCALE + mv.x;
                v[c4*4+1] = sv.y * SCALE + mv.y;
                v[c4*4+2] = sv.z * SCALE + mv.z;
                v[c4*4+3] = sv.w * SCALE + mv.w;
                mx = fmaxf(mx, fmaxf(fmaxf(v[c4*4+0], v[c4*4+1]),
                                     fmaxf(v[c4*4+2], v[c4*4+3])));
            }
            mx = fmaxf(mx, __shfl_xor_sync(0xffffffffu, mx, 1));
            mx = fmaxf(mx, mprev);

            float sum = 0.f;
#pragma unroll
            for (int i = 0; i < 32; i++) {
                v[i] = __expf(v[i] - mx);
                sum += v[i];
            }
            sum += __shfl_xor_sync(0xffffffffu, sum, 1);

            __syncwarp();   // all reads of S row done before P overwrites it

            __nv_bfloat16* ph = (__nv_bfloat16*)(smc + FOFF_S + r * 272) + hf * 32;
            __nv_bfloat16* pl = (__nv_bfloat16*)(smc + FOFF_S + r * 272 + 128) + hf * 32;
#pragma unroll
            for (int i = 0; i < 32; i += 4) {
                __nv_bfloat16 h0 = __float2bfloat16_rn(v[i]);
                __nv_bfloat16 h1 = __float2bfloat16_rn(v[i+1]);
                __nv_bfloat16 h2 = __float2bfloat16_rn(v[i+2]);
                __nv_bfloat16 h3 = __float2bfloat16_rn(v[i+3]);
                __nv_bfloat162 hp0(h0, h1), hp1(h2, h3);
                __nv_bfloat162 lp0(__float2bfloat16_rn(v[i]   - __bfloat162float(h0)),
                                   __float2bfloat16_rn(v[i+1] - __bfloat162float(h1)));
                __nv_bfloat162 lp1(__float2bfloat16_rn(v[i+2] - __bfloat162float(h2)),
                                   __float2bfloat16_rn(v[i+3] - __bfloat162float(h3)));
                *(uint2*)(ph + i) = make_uint2(*(uint32_t*)&hp0, *(uint32_t*)&hp1);
                *(uint2*)(pl + i) = make_uint2(*(uint32_t*)&lp0, *(uint32_t*)&lp1);
            }

            if (hf == 0) {
                float al = __expf(mprev - mx);
                m_s[r]  = mx;
                l_s[r]  = lprev * al + sum;
                al_s[r] = al;
            }
        }
        cp_wait<2>();      // V(t) resident (K(t+1), V(t+1) may be in flight)
        // g. P + stats visible to all warps
        __syncthreads();

        // h. rescale accumulator, then O += P V (bf16x3)
#pragma unroll
        for (int mt = 0; mt < 4; mt++) {
            const int r1 = wm * 64 + mt * 16 + (lane >> 2);
            float al1 = al_s[r1];
            float al2 = al_s[r1 + 8];
#pragma unroll
            for (int j = 0; j < 4; j++) {
                oacc[mt][j][0] *= al1;
                oacc[mt][j][1] *= al1;
                oacc[mt][j][2] *= al2;
                oacc[mt][j][3] *= al2;
            }
        }

#pragma unroll
        for (int t2 = 0; t2 < 4; t2++) {
            uint32_t pa[4][4], pb[4][4], vh_[2][4], vl_[2][4];
#pragma unroll
            for (int mt = 0; mt < 4; mt++) {
                uint32_t addr = sS_u + (a_r + mt * 16) * 272 + t2 * 32 + a_c * 16;
                ldsm4(pa[mt][0], pa[mt][1], pa[mt][2], pa[mt][3], addr);
                ldsm4(pb[mt][0], pb[mt][1], pb[mt][2], pb[mt][3], addr + 128);
            }
#pragma unroll
            for (int jj = 0; jj < 2; jj++) {
                uint32_t addr = vbuf + (t2 * 16 + v_key) * 272 + (v_dd + jj * 16) * 2;
                ldsm4t(vh_[jj][0], vh_[jj][1], vh_[jj][2], vh_[jj][3], addr);
                ldsm4t(vl_[jj][0], vl_[jj][1], vl_[jj][2], vl_[jj][3], addr + 17408);
            }
#pragma unroll
            for (int mt = 0; mt < 4; mt++)
#pragma unroll
                for (int n8 = 0; n8 < 4; n8++) {
                    const int jj = n8 >> 1, p = (n8 & 1) * 2;
                    uint32_t bH[2] = { vh_[jj][p], vh_[jj][p + 1] };
                    uint32_t bL[2] = { vl_[jj][p], vl_[jj][p + 1] };
                    mma16816(oacc[mt][n8], pa[mt], bH);
                    mma16816(oacc[mt][n8], pa[mt], bL);
                    mma16816(oacc[mt][n8], pb[mt], bH);
                }
        }
    }

    // epilogue: /l, bf16 hi/lo split store
#pragma unroll
    for (int mt = 0; mt < 4; mt++) {
        const int r1 = wm * 64 + mt * 16 + (lane >> 2);
        float inv1 = 1.0f / l_s[r1];
        float inv2 = 1.0f / l_s[r1 + 8];
#pragma unroll
        for (int n8 = 0; n8 < 4; n8++) {
            const int cc = wn * 32 + n8 * 8 + ((lane & 3) << 1);
#pragma unroll
            for (int hrow = 0; hrow < 2; hrow++) {
                float o0 = oacc[mt][n8][hrow * 2]     * (hrow ? inv2 : inv1);
                float o1 = oacc[mt][n8][hrow * 2 + 1] * (hrow ? inv2 : inv1);
                size_t off = (size_t)(b * CS + q0 + r1 + hrow * 8) * CD
                           + (size_t)h * CHD + cc;
                __nv_bfloat16 h0 = __float2bfloat16_rn(o0);
                __nv_bfloat16 h1 = __float2bfloat16_rn(o1);
                __nv_bfloat162 hv(h0, h1);
                __nv_bfloat162 lv(__float2bfloat16_rn(o0 - __bfloat162float(h0)),
                                  __float2bfloat16_rn(o1 - __bfloat162float(h1)));
                *(uint32_t*)(&g_aoh[off]) = *(uint32_t*)&hv;
                *(uint32_t*)(&g_aol[off]) = *(uint32_t*)&lv;
            }
        }
    }
}

// ---------------------------------------------------------------------------
extern "C" void kernel_launch(void* const* d_in, const int* in_sizes, int n_in,
                              void* d_out, int out_size)
{
    const float* X    = (const float*)d_in[0];
    const float* mask = (const float*)d_in[1];
    const float* Wq   = (const float*)d_in[2];
    const float* Wk   = (const float*)d_in[3];
    const float* Wv   = (const float*)d_in[4];
    const float* Wo   = (const float*)d_in[5];
    float* out = (float*)d_out;

    float *qp, *kp;
    cudaGetSymbolAddress((void**)&qp, g_q);
    cudaGetSymbolAddress((void**)&kp, g_k);
    __nv_bfloat16 *xh, *xl, *wqh, *wql, *wkh, *wkl, *wvh, *wvl, *woh, *wol, *aoh, *aol;
    __nv_bfloat16 *vh, *vl;
    cudaGetSymbolAddress((void**)&xh,  g_xh);
    cudaGetSymbolAddress((void**)&xl,  g_xl);
    cudaGetSymbolAddress((void**)&wqh, g_wqh);
    cudaGetSymbolAddress((void**)&wql, g_wql);
    cudaGetSymbolAddress((void**)&wkh, g_wkh);
    cudaGetSymbolAddress((void**)&wkl, g_wkl);
    cudaGetSymbolAddress((void**)&wvh, g_wvh);
    cudaGetSymbolAddress((void**)&wvl, g_wvl);
    cudaGetSymbolAddress((void**)&woh, g_woh);
    cudaGetSymbolAddress((void**)&wol, g_wol);
    cudaGetSymbolAddress((void**)&aoh, g_aoh);
    cudaGetSymbolAddress((void**)&aol, g_aol);
    cudaGetSymbolAddress((void**)&vh,  g_vh);
    cudaGetSymbolAddress((void**)&vl,  g_vl);

    cudaFuncSetAttribute(flash_mma, cudaFuncAttributeMaxDynamicSharedMemorySize,
                         FLASH_SMEM);
    cudaFuncSetAttribute(gemm_bf16x3, cudaFuncAttributeMaxDynamicSharedMemorySize,
                         GEMM_SMEM);

    init_invf<<<1, 64>>>();

    const int n4x = CM * CD / 4, n4w = CD * CD / 4;
    convert_hilo<<<dim3(n4x / 256, 1), 256>>>(X, xh, xl, X, xh, xl, X, xh, xl,
                                              X, xh, xl, n4x);
    convert_hilo<<<dim3(n4w / 256, 4), 256>>>(Wq, wqh, wql, Wk, wkh, wkl,
                                              Wv, wvh, wvl, Wo, woh, wol, n4w);

    // fused Q/K/V projections; z==2 (V) writes bf16 hi/lo planes directly
    gemm_bf16x3<<<dim3(CD / 128, CM / 128, 3), 128, GEMM_SMEM>>>(
        xh, xl, wqh, wql, wkh, wkl, wvh, wvl, qp, kp, vh, vl, 2, CD, CD);

    rope_split<<<(CM * CH * 64) / 256, 256>>>();

    flash_mma<<<dim3(CS / 128, CH, CB), 256, FLASH_SMEM>>>(mask);

    // O projection (fp32 out)
    gemm_bf16x3<<<dim3(CD / 128, CM / 128, 1), 128, GEMM_SMEM>>>(
        aoh, aol, woh, wol, woh, wol, woh, wol, out, out, nullptr, nullptr, -1, CD, CD);
}

// round 13
// speedup vs baseline: 1.0202x; 1.0202x over previous
#include <cuda_runtime.h>
#include <cuda_bf16.h>
#include <math.h>
#include <stdint.h>

#define CB 2
#define CS 2048
#define CD 2048
#define CH 16
#define CHD 128
#define CM (CB*CS)          // 4096 rows total
#define SCALE 0.08838834764831845f   // 1/sqrt(128)

// ---------------------------------------------------------------------------
// Scratch (allocation-free rule: static device globals)
// ---------------------------------------------------------------------------
__device__ float g_q[(size_t)CM * CD];
__device__ float g_k[(size_t)CM * CD];
__device__ float g_invf[64];

__device__ __nv_bfloat16 g_xh[(size_t)CM * CD];
__device__ __nv_bfloat16 g_xl[(size_t)CM * CD];
__device__ __nv_bfloat16 g_wqh[(size_t)CD * CD];
__device__ __nv_bfloat16 g_wql[(size_t)CD * CD];
__device__ __nv_bfloat16 g_wkh[(size_t)CD * CD];
__device__ __nv_bfloat16 g_wkl[(size_t)CD * CD];
__device__ __nv_bfloat16 g_wvh[(size_t)CD * CD];
__device__ __nv_bfloat16 g_wvl[(size_t)CD * CD];
__device__ __nv_bfloat16 g_woh[(size_t)CD * CD];
__device__ __nv_bfloat16 g_wol[(size_t)CD * CD];
__device__ __nv_bfloat16 g_aoh[(size_t)CM * CD];
__device__ __nv_bfloat16 g_aol[(size_t)CM * CD];

// bf16 hi/lo planes for attention inputs
__device__ __nv_bfloat16 g_qh[(size_t)CM * CD];
__device__ __nv_bfloat16 g_ql[(size_t)CM * CD];
__device__ __nv_bfloat16 g_kh[(size_t)CM * CD];
__device__ __nv_bfloat16 g_kl[(size_t)CM * CD];
__device__ __nv_bfloat16 g_vh[(size_t)CM * CD];
__device__ __nv_bfloat16 g_vl[(size_t)CM * CD];

// ---------------------------------------------------------------------------
// PTX helpers
// ---------------------------------------------------------------------------
__device__ __forceinline__ uint32_t smem_u32(const void* p) {
    return (uint32_t)__cvta_generic_to_shared(p);
}

__device__ __forceinline__ void ldsm4(uint32_t& r0, uint32_t& r1,
                                      uint32_t& r2, uint32_t& r3, uint32_t addr) {
    asm volatile("ldmatrix.sync.aligned.m8n8.x4.shared.b16 {%0,%1,%2,%3}, [%4];"
                 : "=r"(r0), "=r"(r1), "=r"(r2), "=r"(r3) : "r"(addr));
}

__device__ __forceinline__ void ldsm4t(uint32_t& r0, uint32_t& r1,
                                       uint32_t& r2, uint32_t& r3, uint32_t addr) {
    asm volatile("ldmatrix.sync.aligned.m8n8.x4.trans.shared.b16 {%0,%1,%2,%3}, [%4];"
                 : "=r"(r0), "=r"(r1), "=r"(r2), "=r"(r3) : "r"(addr));
}

__device__ __forceinline__ void mma16816(float* c, const uint32_t* a, const uint32_t* b) {
    asm volatile(
        "mma.sync.aligned.m16n8k16.row.col.f32.bf16.bf16.f32 "
        "{%0,%1,%2,%3}, {%4,%5,%6,%7}, {%8,%9}, {%0,%1,%2,%3};"
        : "+f"(c[0]), "+f"(c[1]), "+f"(c[2]), "+f"(c[3])
        : "r"(a[0]), "r"(a[1]), "r"(a[2]), "r"(a[3]), "r"(b[0]), "r"(b[1]));
}

__device__ __forceinline__ void cp16(uint32_t saddr, const void* gaddr) {
    asm volatile("cp.async.cg.shared.global [%0], [%1], 16;"
                 :: "r"(saddr), "l"(gaddr) : "memory");
}
__device__ __forceinline__ void cp_commit() {
    asm volatile("cp.async.commit_group;" ::: "memory");
}
template <int N>
__device__ __forceinline__ void cp_wait() {
    asm volatile("cp.async.wait_group %0;" :: "n"(N) : "memory");
}

// ---------------------------------------------------------------------------
__global__ void init_invf()
{
    int i = threadIdx.x;
    if (i < 64)
        g_invf[i] = (float)(1.0 / pow(10000.0, (double)(2 * i) / (double)CHD));
}

// ---------------------------------------------------------------------------
// fp32 -> (bf16 hi, bf16 lo) split conversion. 4 elements per thread.
// blockIdx.y selects among up to 4 (src, hi, lo) triples.
// ---------------------------------------------------------------------------
__global__ __launch_bounds__(256) void convert_hilo(
    const float* __restrict__ s0, __nv_bfloat16* __restrict__ h0d, __nv_bfloat16* __restrict__ l0d,
    const float* __restrict__ s1, __nv_bfloat16* __restrict__ h1d, __nv_bfloat16* __restrict__ l1d,
    const float* __restrict__ s2, __nv_bfloat16* __restrict__ h2d, __nv_bfloat16* __restrict__ l2d,
    const float* __restrict__ s3, __nv_bfloat16* __restrict__ h3d, __nv_bfloat16* __restrict__ l3d,
    int n4)
{
    const float* src = (blockIdx.y == 0) ? s0 : (blockIdx.y == 1) ? s1 :
                       (blockIdx.y == 2) ? s2 : s3;
    __nv_bfloat16* hi = (blockIdx.y == 0) ? h0d : (blockIdx.y == 1) ? h1d :
                        (blockIdx.y == 2) ? h2d : h3d;
    __nv_bfloat16* lo = (blockIdx.y == 0) ? l0d : (blockIdx.y == 1) ? l1d :
                        (blockIdx.y == 2) ? l2d : l3d;

    int i = blockIdx.x * 256 + threadIdx.x;
    if (i >= n4) return;
    float4 v = ((const float4*)src)[i];
    __nv_bfloat16 h0 = __float2bfloat16_rn(v.x);
    __nv_bfloat16 h1 = __float2bfloat16_rn(v.y);
    __nv_bfloat16 h2 = __float2bfloat16_rn(v.z);
    __nv_bfloat16 h3 = __float2bfloat16_rn(v.w);
    __nv_bfloat16 l0 = __float2bfloat16_rn(v.x - __bfloat162float(h0));
    __nv_bfloat16 l1 = __float2bfloat16_rn(v.y - __bfloat162float(h1));
    __nv_bfloat16 l2 = __float2bfloat16_rn(v.z - __bfloat162float(h2));
    __nv_bfloat16 l3 = __float2bfloat16_rn(v.w - __bfloat162float(h3));
    ((__nv_bfloat162*)hi)[2 * i]     = __nv_bfloat162(h0, h1);
    ((__nv_bfloat162*)hi)[2 * i + 1] = __nv_bfloat162(h2, h3);
    ((__nv_bfloat162*)lo)[2 * i]     = __nv_bfloat162(l0, l1);
    ((__nv_bfloat162*)lo)[2 * i + 1] = __nv_bfloat162(l2, l3);
}

// ---------------------------------------------------------------------------
// bf16-split tensor-core NT GEMM: 64x32 warp tiles (proven mapping),
// cp.async double buffer, single sync per k-step, 2 CTAs/SM.
// C = Ah Bh^T + Ah Bl^T + Al Bh^T   (fp32 accumulate)
// CTA tile 128x128x32, 256 threads = 8 warps (2x4).
// smem rows: 40 bf16 (80B stride) -> conflict-free ldmatrix phases.
// blockIdx.z selects among up to 3 (B, C) pairs; z == zbf writes bf16 hi/lo.
// ---------------------------------------------------------------------------
#define GPLANE 10240                 // bytes per plane (128 rows x 80B)
#define GSTAGE (4 * GPLANE)          // Ah, Al, Bh, Bl = 40960
#define GEMM_SMEM (2 * GSTAGE)       // 81920 B/CTA; x2 CTAs = 160KB/SM

__global__ __launch_bounds__(256, 2) void gemm_bf16x3(
    const __nv_bfloat16* __restrict__ Ah, const __nv_bfloat16* __restrict__ Al,
    const __nv_bfloat16* __restrict__ Bh0, const __nv_bfloat16* __restrict__ Bl0,
    const __nv_bfloat16* __restrict__ Bh1, const __nv_bfloat16* __restrict__ Bl1,
    const __nv_bfloat16* __restrict__ Bh2, const __nv_bfloat16* __restrict__ Bl2,
    float* __restrict__ C0, float* __restrict__ C1,
    __nv_bfloat16* __restrict__ Cbh, __nv_bfloat16* __restrict__ Cbl, int zbf,
    int N, int K)
{
    extern __shared__ char smg[];
    const uint32_t sb = smem_u32(smg);

    const __nv_bfloat16* Bh = (blockIdx.z == 0) ? Bh0 : (blockIdx.z == 1) ? Bh1 : Bh2;
    const __nv_bfloat16* Bl = (blockIdx.z == 0) ? Bl0 : (blockIdx.z == 1) ? Bl1 : Bl2;
    float*               C  = (blockIdx.z == 0) ? C0  : C1;

    const int tid  = threadIdx.x;
    const int lane = tid & 31;
    const int wid  = tid >> 5;
    const int wm   = wid >> 2;      // 0..1
    const int wn   = wid & 3;       // 0..3
    const int bm   = blockIdx.y << 7;
    const int bn   = blockIdx.x << 7;

    // copy mapping: 512 16B-chunks per plane; thread does j=tid, j=tid+256
    const int crow0 = tid >> 2,        cc0 = tid & 3;
    const int crow1 = 64 + (tid >> 2), cc1 = tid & 3;
    const uint32_t so0 = crow0 * 80 + cc0 * 16;
    const uint32_t so1 = crow1 * 80 + cc1 * 16;
    const size_t gA0 = (size_t)(bm + crow0) * K + cc0 * 8;
    const size_t gA1 = (size_t)(bm + crow1) * K + cc1 * 8;
    const size_t gB0 = (size_t)(bn + crow0) * K + cc0 * 8;
    const size_t gB1 = (size_t)(bn + crow1) * K + cc1 * 8;

    float acc[4][4][4];
#pragma unroll
    for (int i = 0; i < 4; i++)
#pragma unroll
        for (int j = 0; j < 4; j++)
#pragma unroll
            for (int r = 0; r < 4; r++) acc[i][j][r] = 0.f;

    const int a_row = wm * 64 + (lane & 15);
    const int a_ch  = lane >> 4;
    const int b_row = wn * 32 + (lane & 7) + ((lane >> 4) << 3);
    const int b_ch  = (lane >> 3) & 1;

    const int iters = K >> 5;   // 64

    auto issue = [&](int ki) {
        const uint32_t sa = sb + (ki & 1) * GSTAGE;
        const int k0 = ki << 5;
        cp16(sa + so0,              Ah + gA0 + k0);
        cp16(sa + so1,              Ah + gA1 + k0);
        cp16(sa + GPLANE + so0,     Al + gA0 + k0);
        cp16(sa + GPLANE + so1,     Al + gA1 + k0);
        cp16(sa + 2 * GPLANE + so0, Bh + gB0 + k0);
        cp16(sa + 2 * GPLANE + so1, Bh + gB1 + k0);
        cp16(sa + 3 * GPLANE + so0, Bl + gB0 + k0);
        cp16(sa + 3 * GPLANE + so1, Bl + gB1 + k0);
        cp_commit();
    };

    issue(0);

    for (int it = 0; it < iters; it++) {
        cp_wait<0>();          // stage it resident (only it pending here)
        __syncthreads();       // buffer (it+1)&1 fully read by MMA(it-1)

        if (it + 1 < iters) issue(it + 1);

        const uint32_t stage = sb + (it & 1) * GSTAGE;

#pragma unroll
        for (int kh = 0; kh < 2; kh++) {
            uint32_t ah[4][4], al[4][4], bh[4][2], bl[4][2];
#pragma unroll
            for (int mt = 0; mt < 4; mt++) {
                uint32_t addr = stage + (a_row + mt * 16) * 80 + (2 * kh + a_ch) * 16;
                ldsm4(ah[mt][0], ah[mt][1], ah[mt][2], ah[mt][3], addr);
                ldsm4(al[mt][0], al[mt][1], al[mt][2], al[mt][3], addr + GPLANE);
            }
#pragma unroll
            for (int nt = 0; nt < 2; nt++) {
                uint32_t addr = stage + 2 * GPLANE +
                                (b_row + nt * 16) * 80 + (2 * kh + b_ch) * 16;
                ldsm4(bh[nt * 2][0], bh[nt * 2][1],
                      bh[nt * 2 + 1][0], bh[nt * 2 + 1][1], addr);
                ldsm4(bl[nt * 2][0], bl[nt * 2][1],
                      bl[nt * 2 + 1][0], bl[nt * 2 + 1][1], addr + GPLANE);
            }
#pragma unroll
            for (int mt = 0; mt < 4; mt++)
#pragma unroll
                for (int n8 = 0; n8 < 4; n8++) {
                    mma16816(acc[mt][n8], ah[mt], bh[n8]);
                    mma16816(acc[mt][n8], ah[mt], bl[n8]);
                    mma16816(acc[mt][n8], al[mt], bh[n8]);
                }
        }
    }

    if ((int)blockIdx.z == zbf) {
#pragma unroll
        for (int mt = 0; mt < 4; mt++) {
            const int gm = bm + wm * 64 + mt * 16 + (lane >> 2);
#pragma unroll
            for (int n8 = 0; n8 < 4; n8++) {
                const int gc = bn + wn * 32 + n8 * 8 + ((lane & 3) << 1);
#pragma unroll
                for (int hrow = 0; hrow < 2; hrow++) {
                    float o0 = acc[mt][n8][hrow * 2];
                    float o1 = acc[mt][n8][hrow * 2 + 1];
                    size_t off = (size_t)(gm + hrow * 8) * N + gc;
                    __nv_bfloat16 h0 = __float2bfloat16_rn(o0);
                    __nv_bfloat16 h1 = __float2bfloat16_rn(o1);
                    __nv_bfloat162 hv(h0, h1);
                    __nv_bfloat162 lv(__float2bfloat16_rn(o0 - __bfloat162float(h0)),
                                      __float2bfloat16_rn(o1 - __bfloat162float(h1)));
                    *(uint32_t*)(&Cbh[off]) = *(uint32_t*)&hv;
                    *(uint32_t*)(&Cbl[off]) = *(uint32_t*)&lv;
                }
            }
        }
    } else {
#pragma unroll
        for (int mt = 0; mt < 4; mt++) {
            const int gm = bm + wm * 64 + mt * 16 + (lane >> 2);
#pragma unroll
            for (int n8 = 0; n8 < 4; n8++) {
                const int gc = bn + wn * 32 + n8 * 8 + ((lane & 3) << 1);
                *(float2*)(&C[(size_t)gm * N + gc]) =
                    make_float2(acc[mt][n8][0], acc[mt][n8][1]);
                *(float2*)(&C[(size_t)(gm + 8) * N + gc]) =
                    make_float2(acc[mt][n8][2], acc[mt][n8][3]);
            }
        }
    }
}

// ---------------------------------------------------------------------------
// RoPE: reads fp32 g_q/g_k, writes bf16 hi/lo planes qh/ql/kh/kl.
// ---------------------------------------------------------------------------
__global__ __launch_bounds__(256) void rope_split()
{
    int idx = blockIdx.x * 256 + threadIdx.x;
    int i = idx & 63;
    int m = idx >> 10;
    int s = m & (CS - 1);

    float inv = g_invf[i];
    float ang = (float)s * inv;
    float c, sn;
    sincosf(ang, &sn, &c);

    int h = (idx >> 6) & (CH - 1);
    size_t base = (size_t)m * CD + (size_t)h * CHD;

    float q1 = g_q[base + i], q2 = g_q[base + i + 64];
    float rq1 = q1 * c - q2 * sn;
    float rq2 = q2 * c + q1 * sn;
    float k1 = g_k[base + i], k2 = g_k[base + i + 64];
    float rk1 = k1 * c - k2 * sn;
    float rk2 = k2 * c + k1 * sn;

    __nv_bfloat16 h1 = __float2bfloat16_rn(rq1);
    __nv_bfloat16 h2 = __float2bfloat16_rn(rq2);
    g_qh[base + i]      = h1;
    g_qh[base + i + 64] = h2;
    g_ql[base + i]      = __float2bfloat16_rn(rq1 - __bfloat162float(h1));
    g_ql[base + i + 64] = __float2bfloat16_rn(rq2 - __bfloat162float(h2));

    __nv_bfloat16 h3 = __float2bfloat16_rn(rk1);
    __nv_bfloat16 h4 = __float2bfloat16_rn(rk2);
    g_kh[base + i]      = h3;
    g_kh[base + i + 64] = h4;
    g_kl[base + i]      = __float2bfloat16_rn(rk1 - __bfloat162float(h3));
    g_kl[base + i + 64] = __float2bfloat16_rn(rk2 - __bfloat162float(h4));
}

// ---------------------------------------------------------------------------
// Tensor-core flash attention, pipelined 64-col k-tiles (round-10 proven).
// ---------------------------------------------------------------------------
#define FOFF_QH  0
#define FOFF_QL  34816
#define FOFF_KV  69632
#define KVSLOT   34816          // 64 rows x 272B x 2 planes (h @0, l @17408)
#define FOFF_S   174080         // 128 rows x 272B
#define FOFF_ST  208896
#define FLASH_SMEM 210432

__global__ __launch_bounds__(256, 1) void flash_mma(const float* __restrict__ mask)
{
    extern __shared__ char smc[];
    float* m_s  = (float*)(smc + FOFF_ST);
    float* l_s  = m_s + 128;
    float* al_s = l_s + 128;

    const int tid  = threadIdx.x;
    const int lane = tid & 31;
    const int wid  = tid >> 5;
    const int wm   = wid >> 2;      // 0..1
    const int wn   = wid & 3;       // 0..3
    const int b    = blockIdx.z;
    const int h    = blockIdx.y;
    const int q0   = blockIdx.x << 7;

    const __nv_bfloat16* Qhg = g_qh + (size_t)(b * CS + q0) * CD + (size_t)h * CHD;
    const __nv_bfloat16* Qlg = g_ql + (size_t)(b * CS + q0) * CD + (size_t)h * CHD;
    const __nv_bfloat16* Khg = g_kh + (size_t)(b * CS) * CD + (size_t)h * CHD;
    const __nv_bfloat16* Klg = g_kl + (size_t)(b * CS) * CD + (size_t)h * CHD;
    const __nv_bfloat16* Vhg = g_vh + (size_t)(b * CS) * CD + (size_t)h * CHD;
    const __nv_bfloat16* Vlg = g_vl + (size_t)(b * CS) * CD + (size_t)h * CHD;

    const uint32_t sQ_u  = smem_u32(smc) + FOFF_QH;
    const uint32_t sKV_u = smem_u32(smc) + FOFF_KV;
    const uint32_t sS_u  = smem_u32(smc) + FOFF_S;

    // issue helpers: 64-row tile, 2 planes, 8 cp16/thread; always commit
    auto issueK = [&](int t) {
        if (t < 32) {
            const uint32_t buf = sKV_u + ((2 * t) % 3) * KVSLOT;
            const int k0 = t << 6;
            for (int i = tid; i < 1024; i += 256) {
                int r = i >> 4, c = i & 15;
                cp16(buf + r * 272 + c * 16,
                     Khg + (size_t)(k0 + r) * CD + c * 8);
                cp16(buf + 17408 + r * 272 + c * 16,
                     Klg + (size_t)(k0 + r) * CD + c * 8);
            }
        }
        cp_commit();
    };
    auto issueV = [&](int t) {
        if (t < 32) {
            const uint32_t buf = sKV_u + ((2 * t + 1) % 3) * KVSLOT;
            const int k0 = t << 6;
            for (int i = tid; i < 1024; i += 256) {
                int r = i >> 4, c = i & 15;
                cp16(buf + r * 272 + c * 16,
                     Vhg + (size_t)(k0 + r) * CD + c * 8);
                cp16(buf + 17408 + r * 272 + c * 16,
                     Vlg + (size_t)(k0 + r) * CD + c * 8);
            }
        }
        cp_commit();
    };

    // prologue: Q, K0, V0
    for (int i = tid; i < 2048; i += 256) {
        int r = i >> 4, c = i & 15;
        cp16(sQ_u + r * 272 + c * 16,         Qhg + (size_t)r * CD + c * 8);
        cp16(sQ_u + 34816 + r * 272 + c * 16, Qlg + (size_t)r * CD + c * 8);
    }
    cp_commit();
    issueK(0);
    issueV(0);
    if (tid < 128) { m_s[tid] = -INFINITY; l_s[tid] = 0.f; }

    float oacc[4][4][4];
#pragma unroll
    for (int i = 0; i < 4; i++)
#pragma unroll
        for (int j = 0; j < 4; j++)
#pragma unroll
            for (int r = 0; r < 4; r++) oacc[i][j][r] = 0.f;

    // lane address components (validated round-4 mappings)
    const int a_r = wm * 64 + (lane & 15);                 // + mt*16
    const int a_c = lane >> 4;                             // chunk parity
    const int b_r = wn * 16 + (lane & 7) + ((lane >> 4) << 3);
    const int b_c = (lane >> 3) & 1;
    const int v_key = ((lane >> 3) & 1) * 8 + (lane & 7);  // + t2*16
    const int v_dd  = wn * 32 + ((lane >> 4) << 3);        // + jj*16

    for (int t = 0; t < 32; t++) {
        const int k0 = t << 6;
        // a. K(t) resident; all warps past PV(t-1)
        cp_wait<1>();
        __syncthreads();

        // b. prefetch K(t+1) into V(t-1)'s slot (consumed + sync'd)
        issueK(t + 1);

        const uint32_t kbuf = sKV_u + ((2 * t) % 3) * KVSLOT;
        const uint32_t vbuf = sKV_u + ((2 * t + 1) % 3) * KVSLOT;

        // c. S = Q K^T (bf16x3), 64 cols
        float sacc[4][2][4];
#pragma unroll
        for (int i = 0; i < 4; i++)
#pragma unroll
            for (int j = 0; j < 2; j++)
#pragma unroll
                for (int r = 0; r < 4; r++) sacc[i][j][r] = 0.f;

#pragma unroll
        for (int tt = 0; tt < 8; tt++) {
            uint32_t ah[4][4], al[4][4], bh[2][2], bl[2][2];
#pragma unroll
            for (int mt = 0; mt < 4; mt++) {
                uint32_t addr = sQ_u + (a_r + mt * 16) * 272 + (tt * 2 + a_c) * 16;
                ldsm4(ah[mt][0], ah[mt][1], ah[mt][2], ah[mt][3], addr);
                ldsm4(al[mt][0], al[mt][1], al[mt][2], al[mt][3], addr + 34816);
            }
            {
                uint32_t addr = kbuf + b_r * 272 + (tt * 2 + b_c) * 16;
                ldsm4(bh[0][0], bh[0][1], bh[1][0], bh[1][1], addr);
                ldsm4(bl[0][0], bl[0][1], bl[1][0], bl[1][1], addr + 17408);
            }
#pragma unroll
            for (int mt = 0; mt < 4; mt++)
#pragma unroll
                for (int j = 0; j < 2; j++) {
                    mma16816(sacc[mt][j], ah[mt], bh[j]);
                    mma16816(sacc[mt][j], ah[mt], bl[j]);
                    mma16816(sacc[mt][j], al[mt], bh[j]);
                }
        }

        // store S fp32 (row stride 272B = 68 floats)
#pragma unroll
        for (int mt = 0; mt < 4; mt++) {
            const int r1 = wm * 64 + mt * 16 + (lane >> 2);
#pragma unroll
            for (int j = 0; j < 2; j++) {
                const int cc = wn * 16 + j * 8 + ((lane & 3) << 1);
                *(float2*)((float*)(smc + FOFF_S) + r1 * 68 + cc) =
                    make_float2(sacc[mt][j][0], sacc[mt][j][1]);
                *(float2*)((float*)(smc + FOFF_S) + (r1 + 8) * 68 + cc) =
                    make_float2(sacc[mt][j][2], sacc[mt][j][3]);
            }
        }
        // d. S complete; K(t) reads done
        __syncthreads();

        // e. prefetch V(t+1) into K(t)'s slot
        issueV(t + 1);

        // f. online softmax (2 threads/row, 32 cols each); P bf16 planes in place
        {
            const int r  = tid >> 1;
            const int hf = tid & 1;
            const float* mrow = mask + ((size_t)b * CS + (q0 + r)) * CS + k0 + hf * 32;
            const float* srow = (float*)(smc + FOFF_S + r * 272) + hf * 32;
            float v[32];
            float mprev = m_s[r];
            float lprev = l_s[r];

            float mx = -INFINITY;
#pragma unroll
            for (int c4 = 0; c4 < 8; c4++) {
                float4 sv = *(const float4*)(srow + c4 * 4);
                float4 mv = *(const float4*)(mrow + c4 * 4);
                v[c4*4+0] = sv.x * SCALE + mv.x;
                v[c4*4+1] = sv.y * SCALE + mv.y;
                v[c4*4+2] = sv.z * SCALE + mv.z;
                v[c4*4+3] = sv.w * SCALE + mv.w;
                mx = fmaxf(mx, fmaxf(fmaxf(v[c4*4+0], v[c4*4+1]),
                                     fmaxf(v[c4*4+2], v[c4*4+3])));
            }
            mx = fmaxf(mx, __shfl_xor_sync(0xffffffffu, mx, 1));
            mx = fmaxf(mx, mprev);

            float sum = 0.f;
#pragma unroll
            for (int i = 0; i < 32; i++) {
                v[i] = __expf(v[i] - mx);
                sum += v[i];
            }
            sum += __shfl_xor_sync(0xffffffffu, sum, 1);

            __syncwarp();   // all reads of S row done before P overwrites it

            __nv_bfloat16* ph = (__nv_bfloat16*)(smc + FOFF_S + r * 272) + hf * 32;
            __nv_bfloat16* pl = (__nv_bfloat16*)(smc + FOFF_S + r * 272 + 128) + hf * 32;
#pragma unroll
            for (int i = 0; i < 32; i += 4) {
                __nv_bfloat16 h0 = __float2bfloat16_rn(v[i]);
                __nv_bfloat16 h1 = __float2bfloat16_rn(v[i+1]);
                __nv_bfloat16 h2 = __float2bfloat16_rn(v[i+2]);
                __nv_bfloat16 h3 = __float2bfloat16_rn(v[i+3]);
                __nv_bfloat162 hp0(h0, h1), hp1(h2, h3);
                __nv_bfloat162 lp0(__float2bfloat16_rn(v[i]   - __bfloat162float(h0)),
                                   __float2bfloat16_rn(v[i+1] - __bfloat162float(h1)));
                __nv_bfloat162 lp1(__float2bfloat16_rn(v[i+2] - __bfloat162float(h2)),
                                   __float2bfloat16_rn(v[i+3] - __bfloat162float(h3)));
                *(uint2*)(ph + i) = make_uint2(*(uint32_t*)&hp0, *(uint32_t*)&hp1);
                *(uint2*)(pl + i) = make_uint2(*(uint32_t*)&lp0, *(uint32_t*)&lp1);
            }

            if (hf == 0) {
                float al = __expf(mprev - mx);
                m_s[r]  = mx;
                l_s[r]  = lprev * al + sum;
                al_s[r] = al;
            }
        }
        cp_wait<2>();      // V(t) resident (K(t+1), V(t+1) may be in flight)
        // g. P + stats visible to all warps
        __syncthreads();

        // h. rescale accumulator, then O += P V (bf16x3)
#pragma unroll
        for (int mt = 0; mt < 4; mt++) {
            const int r1 = wm * 64 + mt * 16 + (lane >> 2);
            float al1 = al_s[r1];
            float al2 = al_s[r1 + 8];
#pragma unroll
            for (int j = 0; j < 4; j++) {
                oacc[mt][j][0] *= al1;
                oacc[mt][j][1] *= al1;
                oacc[mt][j][2] *= al2;
                oacc[mt][j][3] *= al2;
            }
        }

#pragma unroll
        for (int t2 = 0; t2 < 4; t2++) {
            uint32_t pa[4][4], pb[4][4], vh_[2][4], vl_[2][4];
#pragma unroll
            for (int mt = 0; mt < 4; mt++) {
                uint32_t addr = sS_u + (a_r + mt * 16) * 272 + t2 * 32 + a_c * 16;
                ldsm4(pa[mt][0], pa[mt][1], pa[mt][2], pa[mt][3], addr);
                ldsm4(pb[mt][0], pb[mt][1], pb[mt][2], pb[mt][3], addr + 128);
            }
#pragma unroll
            for (int jj = 0; jj < 2; jj++) {
                uint32_t addr = vbuf + (t2 * 16 + v_key) * 272 + (v_dd + jj * 16) * 2;
                ldsm4t(vh_[jj][0], vh_[jj][1], vh_[jj][2], vh_[jj][3], addr);
                ldsm4t(vl_[jj][0], vl_[jj][1], vl_[jj][2], vl_[jj][3], addr + 17408);
            }
#pragma unroll
            for (int mt = 0; mt < 4; mt++)
#pragma unroll
                for (int n8 = 0; n8 < 4; n8++) {
                    const int jj = n8 >> 1, p = (n8 & 1) * 2;
                    uint32_t bH[2] = { vh_[jj][p], vh_[jj][p + 1] };
                    uint32_t bL[2] = { vl_[jj][p], vl_[jj][p + 1] };
                    mma16816(oacc[mt][n8], pa[mt], bH);
                    mma16816(oacc[mt][n8], pa[mt], bL);
                    mma16816(oacc[mt][n8], pb[mt], bH);
                }
        }
    }

    // epilogue: /l, bf16 hi/lo split store
#pragma unroll
    for (int mt = 0; mt < 4; mt++) {
        const int r1 = wm * 64 + mt * 16 + (lane >> 2);
        float inv1 = 1.0f / l_s[r1];
        float inv2 = 1.0f / l_s[r1 + 8];
#pragma unroll
        for (int n8 = 0; n8 < 4; n8++) {
            const int cc = wn * 32 + n8 * 8 + ((lane & 3) << 1);
#pragma unroll
            for (int hrow = 0; hrow < 2; hrow++) {
                float o0 = oacc[mt][n8][hrow * 2]     * (hrow ? inv2 : inv1);
                float o1 = oacc[mt][n8][hrow * 2 + 1] * (hrow ? inv2 : inv1);
                size_t off = (size_t)(b * CS + q0 + r1 + hrow * 8) * CD
                           + (size_t)h * CHD + cc;
                __nv_bfloat16 h0 = __float2bfloat16_rn(o0);
                __nv_bfloat16 h1 = __float2bfloat16_rn(o1);
                __nv_bfloat162 hv(h0, h1);
                __nv_bfloat162 lv(__float2bfloat16_rn(o0 - __bfloat162float(h0)),
                                  __float2bfloat16_rn(o1 - __bfloat162float(h1)));
                *(uint32_t*)(&g_aoh[off]) = *(uint32_t*)&hv;
                *(uint32_t*)(&g_aol[off]) = *(uint32_t*)&lv;
            }
        }
    }
}

// ---------------------------------------------------------------------------
extern "C" void kernel_launch(void* const* d_in, const int* in_sizes, int n_in,
                              void* d_out, int out_size)
{
    const float* X    = (const float*)d_in[0];
    const float* mask = (const float*)d_in[1];
    const float* Wq   = (const float*)d_in[2];
    const float* Wk   = (const float*)d_in[3];
    const float* Wv   = (const float*)d_in[4];
    const float* Wo   = (const float*)d_in[5];
    float* out = (float*)d_out;

    float *qp, *kp;
    cudaGetSymbolAddress((void**)&qp, g_q);
    cudaGetSymbolAddress((void**)&kp, g_k);
    __nv_bfloat16 *xh, *xl, *wqh, *wql, *wkh, *wkl, *wvh, *wvl, *woh, *wol, *aoh, *aol;
    __nv_bfloat16 *vh, *vl;
    cudaGetSymbolAddress((void**)&xh,  g_xh);
    cudaGetSymbolAddress((void**)&xl,  g_xl);
    cudaGetSymbolAddress((void**)&wqh, g_wqh);
    cudaGetSymbolAddress((void**)&wql, g_wql);
    cudaGetSymbolAddress((void**)&wkh, g_wkh);
    cudaGetSymbolAddress((void**)&wkl, g_wkl);
    cudaGetSymbolAddress((void**)&wvh, g_wvh);
    cudaGetSymbolAddress((void**)&wvl, g_wvl);
    cudaGetSymbolAddress((void**)&woh, g_woh);
    cudaGetSymbolAddress((void**)&wol, g_wol);
    cudaGetSymbolAddress((void**)&aoh, g_aoh);
    cudaGetSymbolAddress((void**)&aol, g_aol);
    cudaGetSymbolAddress((void**)&vh,  g_vh);
    cudaGetSymbolAddress((void**)&vl,  g_vl);

    cudaFuncSetAttribute(flash_mma, cudaFuncAttributeMaxDynamicSharedMemorySize,
                         FLASH_SMEM);
    cudaFuncSetAttribute(gemm_bf16x3, cudaFuncAttributeMaxDynamicSharedMemorySize,
                         GEMM_SMEM);

    init_invf<<<1, 64>>>();

    const int n4x = CM * CD / 4, n4w = CD * CD / 4;
    convert_hilo<<<dim3(n4x / 256, 1), 256>>>(X, xh, xl, X, xh, xl, X, xh, xl,
                                              X, xh, xl, n4x);
    convert_hilo<<<dim3(n4w / 256, 4), 256>>>(Wq, wqh, wql, Wk, wkh, wkl,
                                              Wv, wvh, wvl, Wo, woh, wol, n4w);

    // fused Q/K/V projections; z==2 (V) writes bf16 hi/lo planes directly
    gemm_bf16x3<<<dim3(CD / 128, CM / 128, 3), 256, GEMM_SMEM>>>(
        xh, xl, wqh, wql, wkh, wkl, wvh, wvl, qp, kp, vh, vl, 2, CD, CD);

    rope_split<<<(CM * CH * 64) / 256, 256>>>();

    flash_mma<<<dim3(CS / 128, CH, CB), 256, FLASH_SMEM>>>(mask);

    // O projection (fp32 out)
    gemm_bf16x3<<<dim3(CD / 128, CM / 128, 1), 256, GEMM_SMEM>>>(
        aoh, aol, woh, wol, woh, wol, woh, wol, out, out, nullptr, nullptr, -1, CD, CD);
}

// round 14
// speedup vs baseline: 1.1102x; 1.0883x over previous
#include <cuda_runtime.h>
#include <cuda_bf16.h>
#include <math.h>
#include <stdint.h>

#define CB 2
#define CS 2048
#define CD 2048
#define CH 16
#define CHD 128
#define CM (CB*CS)          // 4096 rows total
#define SCALE 0.08838834764831845f   // 1/sqrt(128)

// ---------------------------------------------------------------------------
// Scratch (allocation-free rule: static device globals)
// ---------------------------------------------------------------------------
__device__ float g_q[(size_t)CM * CD];
__device__ float g_k[(size_t)CM * CD];
__device__ float g_invf[64];

__device__ __nv_bfloat16 g_xh[(size_t)CM * CD];
__device__ __nv_bfloat16 g_xl[(size_t)CM * CD];
__device__ __nv_bfloat16 g_wqh[(size_t)CD * CD];
__device__ __nv_bfloat16 g_wql[(size_t)CD * CD];
__device__ __nv_bfloat16 g_wkh[(size_t)CD * CD];
__device__ __nv_bfloat16 g_wkl[(size_t)CD * CD];
__device__ __nv_bfloat16 g_wvh[(size_t)CD * CD];
__device__ __nv_bfloat16 g_wvl[(size_t)CD * CD];
__device__ __nv_bfloat16 g_woh[(size_t)CD * CD];
__device__ __nv_bfloat16 g_wol[(size_t)CD * CD];
__device__ __nv_bfloat16 g_aoh[(size_t)CM * CD];
__device__ __nv_bfloat16 g_aol[(size_t)CM * CD];

// bf16 hi/lo planes for attention inputs
__device__ __nv_bfloat16 g_qh[(size_t)CM * CD];
__device__ __nv_bfloat16 g_ql[(size_t)CM * CD];
__device__ __nv_bfloat16 g_kh[(size_t)CM * CD];
__device__ __nv_bfloat16 g_kl[(size_t)CM * CD];
__device__ __nv_bfloat16 g_vh[(size_t)CM * CD];
__device__ __nv_bfloat16 g_vl[(size_t)CM * CD];

// ---------------------------------------------------------------------------
// PTX helpers
// ---------------------------------------------------------------------------
__device__ __forceinline__ uint32_t smem_u32(const void* p) {
    return (uint32_t)__cvta_generic_to_shared(p);
}

__device__ __forceinline__ void ldsm4(uint32_t& r0, uint32_t& r1,
                                      uint32_t& r2, uint32_t& r3, uint32_t addr) {
    asm volatile("ldmatrix.sync.aligned.m8n8.x4.shared.b16 {%0,%1,%2,%3}, [%4];"
                 : "=r"(r0), "=r"(r1), "=r"(r2), "=r"(r3) : "r"(addr));
}

__device__ __forceinline__ void ldsm4t(uint32_t& r0, uint32_t& r1,
                                       uint32_t& r2, uint32_t& r3, uint32_t addr) {
    asm volatile("ldmatrix.sync.aligned.m8n8.x4.trans.shared.b16 {%0,%1,%2,%3}, [%4];"
                 : "=r"(r0), "=r"(r1), "=r"(r2), "=r"(r3) : "r"(addr));
}

__device__ __forceinline__ void mma16816(float* c, const uint32_t* a, const uint32_t* b) {
    asm volatile(
        "mma.sync.aligned.m16n8k16.row.col.f32.bf16.bf16.f32 "
        "{%0,%1,%2,%3}, {%4,%5,%6,%7}, {%8,%9}, {%0,%1,%2,%3};"
        : "+f"(c[0]), "+f"(c[1]), "+f"(c[2]), "+f"(c[3])
        : "r"(a[0]), "r"(a[1]), "r"(a[2]), "r"(a[3]), "r"(b[0]), "r"(b[1]));
}

__device__ __forceinline__ void cp16(uint32_t saddr, const void* gaddr) {
    asm volatile("cp.async.cg.shared.global [%0], [%1], 16;"
                 :: "r"(saddr), "l"(gaddr) : "memory");
}
__device__ __forceinline__ void cp_commit() {
    asm volatile("cp.async.commit_group;" ::: "memory");
}
template <int N>
__device__ __forceinline__ void cp_wait() {
    asm volatile("cp.async.wait_group %0;" :: "n"(N) : "memory");
}

// ---------------------------------------------------------------------------
__global__ void init_invf()
{
    int i = threadIdx.x;
    if (i < 64)
        g_invf[i] = (float)(1.0 / pow(10000.0, (double)(2 * i) / (double)CHD));
}

// ---------------------------------------------------------------------------
// fp32 -> (bf16 hi, bf16 lo) split conversion. 4 elements per thread.
// blockIdx.y selects among up to 4 (src, hi, lo) triples.
// ---------------------------------------------------------------------------
__global__ __launch_bounds__(256) void convert_hilo(
    const float* __restrict__ s0, __nv_bfloat16* __restrict__ h0d, __nv_bfloat16* __restrict__ l0d,
    const float* __restrict__ s1, __nv_bfloat16* __restrict__ h1d, __nv_bfloat16* __restrict__ l1d,
    const float* __restrict__ s2, __nv_bfloat16* __restrict__ h2d, __nv_bfloat16* __restrict__ l2d,
    const float* __restrict__ s3, __nv_bfloat16* __restrict__ h3d, __nv_bfloat16* __restrict__ l3d,
    int n4)
{
    const float* src = (blockIdx.y == 0) ? s0 : (blockIdx.y == 1) ? s1 :
                       (blockIdx.y == 2) ? s2 : s3;
    __nv_bfloat16* hi = (blockIdx.y == 0) ? h0d : (blockIdx.y == 1) ? h1d :
                        (blockIdx.y == 2) ? h2d : h3d;
    __nv_bfloat16* lo = (blockIdx.y == 0) ? l0d : (blockIdx.y == 1) ? l1d :
                        (blockIdx.y == 2) ? l2d : l3d;

    int i = blockIdx.x * 256 + threadIdx.x;
    if (i >= n4) return;
    float4 v = ((const float4*)src)[i];
    __nv_bfloat16 h0 = __float2bfloat16_rn(v.x);
    __nv_bfloat16 h1 = __float2bfloat16_rn(v.y);
    __nv_bfloat16 h2 = __float2bfloat16_rn(v.z);
    __nv_bfloat16 h3 = __float2bfloat16_rn(v.w);
    __nv_bfloat16 l0 = __float2bfloat16_rn(v.x - __bfloat162float(h0));
    __nv_bfloat16 l1 = __float2bfloat16_rn(v.y - __bfloat162float(h1));
    __nv_bfloat16 l2 = __float2bfloat16_rn(v.z - __bfloat162float(h2));
    __nv_bfloat16 l3 = __float2bfloat16_rn(v.w - __bfloat162float(h3));
    ((__nv_bfloat162*)hi)[2 * i]     = __nv_bfloat162(h0, h1);
    ((__nv_bfloat162*)hi)[2 * i + 1] = __nv_bfloat162(h2, h3);
    ((__nv_bfloat162*)lo)[2 * i]     = __nv_bfloat162(l0, l1);
    ((__nv_bfloat162*)lo)[2 * i + 1] = __nv_bfloat162(l2, l3);
}

// ---------------------------------------------------------------------------
// bf16-split tensor-core NT GEMM: 64x32 warp tiles, cp.async double buffer,
// single sync per k-step, 2 CTAs/SM (round-13 proven, best so far).
// C = Ah Bh^T + Ah Bl^T + Al Bh^T   (fp32 accumulate)
// ---------------------------------------------------------------------------
#define GPLANE 10240
#define GSTAGE (4 * GPLANE)
#define GEMM_SMEM (2 * GSTAGE)

__global__ __launch_bounds__(256, 2) void gemm_bf16x3(
    const __nv_bfloat16* __restrict__ Ah, const __nv_bfloat16* __restrict__ Al,
    const __nv_bfloat16* __restrict__ Bh0, const __nv_bfloat16* __restrict__ Bl0,
    const __nv_bfloat16* __restrict__ Bh1, const __nv_bfloat16* __restrict__ Bl1,
    const __nv_bfloat16* __restrict__ Bh2, const __nv_bfloat16* __restrict__ Bl2,
    float* __restrict__ C0, float* __restrict__ C1,
    __nv_bfloat16* __restrict__ Cbh, __nv_bfloat16* __restrict__ Cbl, int zbf,
    int N, int K)
{
    extern __shared__ char smg[];
    const uint32_t sb = smem_u32(smg);

    const __nv_bfloat16* Bh = (blockIdx.z == 0) ? Bh0 : (blockIdx.z == 1) ? Bh1 : Bh2;
    const __nv_bfloat16* Bl = (blockIdx.z == 0) ? Bl0 : (blockIdx.z == 1) ? Bl1 : Bl2;
    float*               C  = (blockIdx.z == 0) ? C0  : C1;

    const int tid  = threadIdx.x;
    const int lane = tid & 31;
    const int wid  = tid >> 5;
    const int wm   = wid >> 2;
    const int wn   = wid & 3;
    const int bm   = blockIdx.y << 7;
    const int bn   = blockIdx.x << 7;

    const int crow0 = tid >> 2,        cc0 = tid & 3;
    const int crow1 = 64 + (tid >> 2), cc1 = tid & 3;
    const uint32_t so0 = crow0 * 80 + cc0 * 16;
    const uint32_t so1 = crow1 * 80 + cc1 * 16;
    const size_t gA0 = (size_t)(bm + crow0) * K + cc0 * 8;
    const size_t gA1 = (size_t)(bm + crow1) * K + cc1 * 8;
    const size_t gB0 = (size_t)(bn + crow0) * K + cc0 * 8;
    const size_t gB1 = (size_t)(bn + crow1) * K + cc1 * 8;

    float acc[4][4][4];
#pragma unroll
    for (int i = 0; i < 4; i++)
#pragma unroll
        for (int j = 0; j < 4; j++)
#pragma unroll
            for (int r = 0; r < 4; r++) acc[i][j][r] = 0.f;

    const int a_row = wm * 64 + (lane & 15);
    const int a_ch  = lane >> 4;
    const int b_row = wn * 32 + (lane & 7) + ((lane >> 4) << 3);
    const int b_ch  = (lane >> 3) & 1;

    const int iters = K >> 5;

    auto issue = [&](int ki) {
        const uint32_t sa = sb + (ki & 1) * GSTAGE;
        const int k0 = ki << 5;
        cp16(sa + so0,              Ah + gA0 + k0);
        cp16(sa + so1,              Ah + gA1 + k0);
        cp16(sa + GPLANE + so0,     Al + gA0 + k0);
        cp16(sa + GPLANE + so1,     Al + gA1 + k0);
        cp16(sa + 2 * GPLANE + so0, Bh + gB0 + k0);
        cp16(sa + 2 * GPLANE + so1, Bh + gB1 + k0);
        cp16(sa + 3 * GPLANE + so0, Bl + gB0 + k0);
        cp16(sa + 3 * GPLANE + so1, Bl + gB1 + k0);
        cp_commit();
    };

    issue(0);

    for (int it = 0; it < iters; it++) {
        cp_wait<0>();
        __syncthreads();

        if (it + 1 < iters) issue(it + 1);

        const uint32_t stage = sb + (it & 1) * GSTAGE;

#pragma unroll
        for (int kh = 0; kh < 2; kh++) {
            uint32_t ah[4][4], al[4][4], bh[4][2], bl[4][2];
#pragma unroll
            for (int mt = 0; mt < 4; mt++) {
                uint32_t addr = stage + (a_row + mt * 16) * 80 + (2 * kh + a_ch) * 16;
                ldsm4(ah[mt][0], ah[mt][1], ah[mt][2], ah[mt][3], addr);
                ldsm4(al[mt][0], al[mt][1], al[mt][2], al[mt][3], addr + GPLANE);
            }
#pragma unroll
            for (int nt = 0; nt < 2; nt++) {
                uint32_t addr = stage + 2 * GPLANE +
                                (b_row + nt * 16) * 80 + (2 * kh + b_ch) * 16;
                ldsm4(bh[nt * 2][0], bh[nt * 2][1],
                      bh[nt * 2 + 1][0], bh[nt * 2 + 1][1], addr);
                ldsm4(bl[nt * 2][0], bl[nt * 2][1],
                      bl[nt * 2 + 1][0], bl[nt * 2 + 1][1], addr + GPLANE);
            }
#pragma unroll
            for (int mt = 0; mt < 4; mt++)
#pragma unroll
                for (int n8 = 0; n8 < 4; n8++) {
                    mma16816(acc[mt][n8], ah[mt], bh[n8]);
                    mma16816(acc[mt][n8], ah[mt], bl[n8]);
                    mma16816(acc[mt][n8], al[mt], bh[n8]);
                }
        }
    }

    if ((int)blockIdx.z == zbf) {
#pragma unroll
        for (int mt = 0; mt < 4; mt++) {
            const int gm = bm + wm * 64 + mt * 16 + (lane >> 2);
#pragma unroll
            for (int n8 = 0; n8 < 4; n8++) {
                const int gc = bn + wn * 32 + n8 * 8 + ((lane & 3) << 1);
#pragma unroll
                for (int hrow = 0; hrow < 2; hrow++) {
                    float o0 = acc[mt][n8][hrow * 2];
                    float o1 = acc[mt][n8][hrow * 2 + 1];
                    size_t off = (size_t)(gm + hrow * 8) * N + gc;
                    __nv_bfloat16 h0 = __float2bfloat16_rn(o0);
                    __nv_bfloat16 h1 = __float2bfloat16_rn(o1);
                    __nv_bfloat162 hv(h0, h1);
                    __nv_bfloat162 lv(__float2bfloat16_rn(o0 - __bfloat162float(h0)),
                                      __float2bfloat16_rn(o1 - __bfloat162float(h1)));
                    *(uint32_t*)(&Cbh[off]) = *(uint32_t*)&hv;
                    *(uint32_t*)(&Cbl[off]) = *(uint32_t*)&lv;
                }
            }
        }
    } else {
#pragma unroll
        for (int mt = 0; mt < 4; mt++) {
            const int gm = bm + wm * 64 + mt * 16 + (lane >> 2);
#pragma unroll
            for (int n8 = 0; n8 < 4; n8++) {
                const int gc = bn + wn * 32 + n8 * 8 + ((lane & 3) << 1);
                *(float2*)(&C[(size_t)gm * N + gc]) =
                    make_float2(acc[mt][n8][0], acc[mt][n8][1]);
                *(float2*)(&C[(size_t)(gm + 8) * N + gc]) =
                    make_float2(acc[mt][n8][2], acc[mt][n8][3]);
            }
        }
    }
}

// ---------------------------------------------------------------------------
// RoPE: reads fp32 g_q/g_k, writes bf16 hi/lo planes qh/ql/kh/kl.
// ---------------------------------------------------------------------------
__global__ __launch_bounds__(256) void rope_split()
{
    int idx = blockIdx.x * 256 + threadIdx.x;
    int i = idx & 63;
    int m = idx >> 10;
    int s = m & (CS - 1);

    float inv = g_invf[i];
    float ang = (float)s * inv;
    float c, sn;
    sincosf(ang, &sn, &c);

    int h = (idx >> 6) & (CH - 1);
    size_t base = (size_t)m * CD + (size_t)h * CHD;

    float q1 = g_q[base + i], q2 = g_q[base + i + 64];
    float rq1 = q1 * c - q2 * sn;
    float rq2 = q2 * c + q1 * sn;
    float k1 = g_k[base + i], k2 = g_k[base + i + 64];
    float rk1 = k1 * c - k2 * sn;
    float rk2 = k2 * c + k1 * sn;

    __nv_bfloat16 h1 = __float2bfloat16_rn(rq1);
    __nv_bfloat16 h2 = __float2bfloat16_rn(rq2);
    g_qh[base + i]      = h1;
    g_qh[base + i + 64] = h2;
    g_ql[base + i]      = __float2bfloat16_rn(rq1 - __bfloat162float(h1));
    g_ql[base + i + 64] = __float2bfloat16_rn(rq2 - __bfloat162float(h2));

    __nv_bfloat16 h3 = __float2bfloat16_rn(rk1);
    __nv_bfloat16 h4 = __float2bfloat16_rn(rk2);
    g_kh[base + i]      = h3;
    g_kh[base + i + 64] = h4;
    g_kl[base + i]      = __float2bfloat16_rn(rk1 - __bfloat162float(h3));
    g_kl[base + i + 64] = __float2bfloat16_rn(rk2 - __bfloat162float(h4));
}

// ---------------------------------------------------------------------------
// Flash attention, FA2-style: warp owns 16 full rows; softmax + P entirely in
// registers (QK C-fragment layout == PV A-fragment layout). Pipelined 64-col
// k-tiles with 3-slot K/V cp.async ring (round-10 proven ring/schedule).
// smem: Q planes (2x34816) + 3 KV slots (3x34816) = 174080 B. No S, no stats.
// ---------------------------------------------------------------------------
#define FOFF_QH  0
#define FOFF_QL  34816
#define FOFF_KV  69632
#define KVSLOT   34816          // 64 rows x 272B x 2 planes (h @0, l @17408)
#define FLASH_SMEM 174080

__global__ __launch_bounds__(256, 1) void flash_mma(const float* __restrict__ mask)
{
    extern __shared__ char smc[];

    const int tid  = threadIdx.x;
    const int lane = tid & 31;
    const int wid  = tid >> 5;      // 0..7: warp owns rows wid*16..wid*16+15
    const int b    = blockIdx.z;
    const int h    = blockIdx.y;
    const int q0   = blockIdx.x << 7;

    const __nv_bfloat16* Qhg = g_qh + (size_t)(b * CS + q0) * CD + (size_t)h * CHD;
    const __nv_bfloat16* Qlg = g_ql + (size_t)(b * CS + q0) * CD + (size_t)h * CHD;
    const __nv_bfloat16* Khg = g_kh + (size_t)(b * CS) * CD + (size_t)h * CHD;
    const __nv_bfloat16* Klg = g_kl + (size_t)(b * CS) * CD + (size_t)h * CHD;
    const __nv_bfloat16* Vhg = g_vh + (size_t)(b * CS) * CD + (size_t)h * CHD;
    const __nv_bfloat16* Vlg = g_vl + (size_t)(b * CS) * CD + (size_t)h * CHD;

    const uint32_t sQ_u  = smem_u32(smc) + FOFF_QH;
    const uint32_t sKV_u = smem_u32(smc) + FOFF_KV;

    auto issueK = [&](int t) {
        if (t < 32) {
            const uint32_t buf = sKV_u + ((2 * t) % 3) * KVSLOT;
            const int k0 = t << 6;
            for (int i = tid; i < 1024; i += 256) {
                int r = i >> 4, c = i & 15;
                cp16(buf + r * 272 + c * 16,
                     Khg + (size_t)(k0 + r) * CD + c * 8);
                cp16(buf + 17408 + r * 272 + c * 16,
                     Klg + (size_t)(k0 + r) * CD + c * 8);
            }
        }
        cp_commit();
    };
    auto issueV = [&](int t) {
        if (t < 32) {
            const uint32_t buf = sKV_u + ((2 * t + 1) % 3) * KVSLOT;
            const int k0 = t << 6;
            for (int i = tid; i < 1024; i += 256) {
                int r = i >> 4, c = i & 15;
                cp16(buf + r * 272 + c * 16,
                     Vhg + (size_t)(k0 + r) * CD + c * 8);
                cp16(buf + 17408 + r * 272 + c * 16,
                     Vlg + (size_t)(k0 + r) * CD + c * 8);
            }
        }
        cp_commit();
    };

    // prologue: Q, K0, V0
    for (int i = tid; i < 2048; i += 256) {
        int r = i >> 4, c = i & 15;
        cp16(sQ_u + r * 272 + c * 16,         Qhg + (size_t)r * CD + c * 8);
        cp16(sQ_u + 34816 + r * 272 + c * 16, Qlg + (size_t)r * CD + c * 8);
    }
    cp_commit();
    issueK(0);
    issueV(0);

    // per-thread state: two rows (r0 = wid*16 + lane/4, r1 = r0 + 8)
    float m_pr0 = -INFINITY, m_pr1 = -INFINITY;
    float l_pr0 = 0.f,       l_pr1 = 0.f;
    float oacc[16][4];
#pragma unroll
    for (int i = 0; i < 16; i++)
#pragma unroll
        for (int r = 0; r < 4; r++) oacc[i][r] = 0.f;

    // lane address components (proven formulas, warp tile = 16 rows)
    const int a_r   = wid * 16 + (lane & 15);
    const int a_c   = lane >> 4;
    const int b_r16 = (lane & 7) + ((lane >> 4) << 3);
    const int b_c   = (lane >> 3) & 1;
    const int v_key = ((lane >> 3) & 1) * 8 + (lane & 7);
    const int v_cg  = (lane >> 4) << 3;
    const int row0  = wid * 16 + (lane >> 2);
    const int colb  = (lane & 3) << 1;

    const float* mrow0 = mask + ((size_t)b * CS + (q0 + row0)) * CS;
    const float* mrow1 = mrow0 + (size_t)8 * CS;

    for (int t = 0; t < 32; t++) {
        const int k0 = t << 6;
        // K(t) resident; all warps past PV(t-1)
        cp_wait<1>();
        __syncthreads();
        issueK(t + 1);   // into V(t-1)'s slot

        const uint32_t kbuf = sKV_u + ((2 * t) % 3) * KVSLOT;
        const uint32_t vbuf = sKV_u + ((2 * t + 1) % 3) * KVSLOT;

        // prefetch mask values for this tile into registers (hidden under MMA)
        float2 mr0[8], mr1[8];
#pragma unroll
        for (int n8 = 0; n8 < 8; n8++) {
            mr0[n8] = *(const float2*)(mrow0 + k0 + n8 * 8 + colb);
            mr1[n8] = *(const float2*)(mrow1 + k0 + n8 * 8 + colb);
        }

        // ---- S = Q K^T (bf16x3): warp computes 16 rows x 64 cols ----
        float sacc[8][4];
#pragma unroll
        for (int i = 0; i < 8; i++)
#pragma unroll
            for (int r = 0; r < 4; r++) sacc[i][r] = 0.f;

#pragma unroll
        for (int tt = 0; tt < 8; tt++) {
            uint32_t aF[4], aL[4], bh[8][2], bl[8][2];
            {
                uint32_t addr = sQ_u + a_r * 272 + (tt * 2 + a_c) * 16;
                ldsm4(aF[0], aF[1], aF[2], aF[3], addr);
                ldsm4(aL[0], aL[1], aL[2], aL[3], addr + 34816);
            }
#pragma unroll
            for (int g = 0; g < 4; g++) {
                uint32_t addr = kbuf + (g * 16 + b_r16) * 272 + (tt * 2 + b_c) * 16;
                ldsm4(bh[2*g][0], bh[2*g][1], bh[2*g+1][0], bh[2*g+1][1], addr);
                ldsm4(bl[2*g][0], bl[2*g][1], bl[2*g+1][0], bl[2*g+1][1], addr + 17408);
            }
#pragma unroll
            for (int n8 = 0; n8 < 8; n8++) {
                mma16816(sacc[n8], aF, bh[n8]);
                mma16816(sacc[n8], aF, bl[n8]);
                mma16816(sacc[n8], aL, bh[n8]);
            }
        }
        __syncthreads();   // all warps done reading K(t) slot
        issueV(t + 1);     // into K(t)'s slot

        // ---- register softmax (rows r0, r1 private to this lane group) ----
        float mx0 = -INFINITY, mx1 = -INFINITY;
#pragma unroll
        for (int n8 = 0; n8 < 8; n8++) {
            sacc[n8][0] = sacc[n8][0] * SCALE + mr0[n8].x;
            sacc[n8][1] = sacc[n8][1] * SCALE + mr0[n8].y;
            sacc[n8][2] = sacc[n8][2] * SCALE + mr1[n8].x;
            sacc[n8][3] = sacc[n8][3] * SCALE + mr1[n8].y;
            mx0 = fmaxf(mx0, fmaxf(sacc[n8][0], sacc[n8][1]));
            mx1 = fmaxf(mx1, fmaxf(sacc[n8][2], sacc[n8][3]));
        }
        mx0 = fmaxf(mx0, __shfl_xor_sync(0xffffffffu, mx0, 1));
        mx0 = fmaxf(mx0, __shfl_xor_sync(0xffffffffu, mx0, 2));
        mx1 = fmaxf(mx1, __shfl_xor_sync(0xffffffffu, mx1, 1));
        mx1 = fmaxf(mx1, __shfl_xor_sync(0xffffffffu, mx1, 2));
        mx0 = fmaxf(mx0, m_pr0);
        mx1 = fmaxf(mx1, m_pr1);
        const float al0 = __expf(m_pr0 - mx0);
        const float al1 = __expf(m_pr1 - mx1);

        float sum0 = 0.f, sum1 = 0.f;
        uint32_t ph0[8], ph1[8], pl0[8], pl1[8];
#pragma unroll
        for (int n8 = 0; n8 < 8; n8++) {
            float p0 = __expf(sacc[n8][0] - mx0);
            float p1 = __expf(sacc[n8][1] - mx0);
            float p2 = __expf(sacc[n8][2] - mx1);
            float p3 = __expf(sacc[n8][3] - mx1);
            sum0 += p0 + p1;
            sum1 += p2 + p3;
            __nv_bfloat16 h0 = __float2bfloat16_rn(p0);
            __nv_bfloat16 h1 = __float2bfloat16_rn(p1);
            __nv_bfloat16 h2 = __float2bfloat16_rn(p2);
            __nv_bfloat16 h3 = __float2bfloat16_rn(p3);
            __nv_bfloat162 hv0(h0, h1), hv1(h2, h3);
            __nv_bfloat162 lv0(__float2bfloat16_rn(p0 - __bfloat162float(h0)),
                               __float2bfloat16_rn(p1 - __bfloat162float(h1)));
            __nv_bfloat162 lv1(__float2bfloat16_rn(p2 - __bfloat162float(h2)),
                               __float2bfloat16_rn(p3 - __bfloat162float(h3)));
            ph0[n8] = *(uint32_t*)&hv0;
            ph1[n8] = *(uint32_t*)&hv1;
            pl0[n8] = *(uint32_t*)&lv0;
            pl1[n8] = *(uint32_t*)&lv1;
        }
        sum0 += __shfl_xor_sync(0xffffffffu, sum0, 1);
        sum0 += __shfl_xor_sync(0xffffffffu, sum0, 2);
        sum1 += __shfl_xor_sync(0xffffffffu, sum1, 1);
        sum1 += __shfl_xor_sync(0xffffffffu, sum1, 2);
        l_pr0 = l_pr0 * al0 + sum0;
        l_pr1 = l_pr1 * al1 + sum1;
        m_pr0 = mx0;
        m_pr1 = mx1;

        // rescale output accumulator
#pragma unroll
        for (int n8 = 0; n8 < 16; n8++) {
            oacc[n8][0] *= al0;
            oacc[n8][1] *= al0;
            oacc[n8][2] *= al1;
            oacc[n8][3] *= al1;
        }

        cp_wait<2>();      // V(t) resident (K(t+1), V(t+1) in flight)
        __syncthreads();   // V(t) writes visible to all warps

        // ---- O += P V (bf16x3): A-frags straight from P registers ----
#pragma unroll
        for (int kt = 0; kt < 4; kt++) {
            uint32_t paH[4] = { ph0[2*kt], ph1[2*kt], ph0[2*kt+1], ph1[2*kt+1] };
            uint32_t paL[4] = { pl0[2*kt], pl1[2*kt], pl0[2*kt+1], pl1[2*kt+1] };
#pragma unroll
            for (int g = 0; g < 8; g++) {
                uint32_t vh[4], vl[4];
                uint32_t addr = vbuf + (kt * 16 + v_key) * 272 + (g * 16 + v_cg) * 2;
                ldsm4t(vh[0], vh[1], vh[2], vh[3], addr);
                ldsm4t(vl[0], vl[1], vl[2], vl[3], addr + 17408);
                uint32_t bH0[2] = { vh[0], vh[1] }, bL0[2] = { vl[0], vl[1] };
                uint32_t bH1[2] = { vh[2], vh[3] }, bL1[2] = { vl[2], vl[3] };
                mma16816(oacc[2*g],     paH, bH0);
                mma16816(oacc[2*g],     paH, bL0);
                mma16816(oacc[2*g],     paL, bH0);
                mma16816(oacc[2*g+1],   paH, bH1);
                mma16816(oacc[2*g+1],   paH, bL1);
                mma16816(oacc[2*g+1],   paL, bH1);
            }
        }
    }

    // epilogue: /l, bf16 hi/lo split store (rows row0, row0+8)
    const float inv0 = 1.0f / l_pr0;
    const float inv1 = 1.0f / l_pr1;
#pragma unroll
    for (int n8 = 0; n8 < 16; n8++) {
        const int cc = n8 * 8 + colb;
#pragma unroll
        for (int hrow = 0; hrow < 2; hrow++) {
            float o0 = oacc[n8][hrow * 2]     * (hrow ? inv1 : inv0);
            float o1 = oacc[n8][hrow * 2 + 1] * (hrow ? inv1 : inv0);
            size_t off = (size_t)(b * CS + q0 + row0 + hrow * 8) * CD
                       + (size_t)h * CHD + cc;
            __nv_bfloat16 h0 = __float2bfloat16_rn(o0);
            __nv_bfloat16 h1 = __float2bfloat16_rn(o1);
            __nv_bfloat162 hv(h0, h1);
            __nv_bfloat162 lv(__float2bfloat16_rn(o0 - __bfloat162float(h0)),
                              __float2bfloat16_rn(o1 - __bfloat162float(h1)));
            *(uint32_t*)(&g_aoh[off]) = *(uint32_t*)&hv;
            *(uint32_t*)(&g_aol[off]) = *(uint32_t*)&lv;
        }
    }
}

// ---------------------------------------------------------------------------
extern "C" void kernel_launch(void* const* d_in, const int* in_sizes, int n_in,
                              void* d_out, int out_size)
{
    const float* X    = (const float*)d_in[0];
    const float* mask = (const float*)d_in[1];
    const float* Wq   = (const float*)d_in[2];
    const float* Wk   = (const float*)d_in[3];
    const float* Wv   = (const float*)d_in[4];
    const float* Wo   = (const float*)d_in[5];
    float* out = (float*)d_out;

    float *qp, *kp;
    cudaGetSymbolAddress((void**)&qp, g_q);
    cudaGetSymbolAddress((void**)&kp, g_k);
    __nv_bfloat16 *xh, *xl, *wqh, *wql, *wkh, *wkl, *wvh, *wvl, *woh, *wol, *aoh, *aol;
    __nv_bfloat16 *vh, *vl;
    cudaGetSymbolAddress((void**)&xh,  g_xh);
    cudaGetSymbolAddress((void**)&xl,  g_xl);
    cudaGetSymbolAddress((void**)&wqh, g_wqh);
    cudaGetSymbolAddress((void**)&wql, g_wql);
    cudaGetSymbolAddress((void**)&wkh, g_wkh);
    cudaGetSymbolAddress((void**)&wkl, g_wkl);
    cudaGetSymbolAddress((void**)&wvh, g_wvh);
    cudaGetSymbolAddress((void**)&wvl, g_wvl);
    cudaGetSymbolAddress((void**)&woh, g_woh);
    cudaGetSymbolAddress((void**)&wol, g_wol);
    cudaGetSymbolAddress((void**)&aoh, g_aoh);
    cudaGetSymbolAddress((void**)&aol, g_aol);
    cudaGetSymbolAddress((void**)&vh,  g_vh);
    cudaGetSymbolAddress((void**)&vl,  g_vl);

    cudaFuncSetAttribute(flash_mma, cudaFuncAttributeMaxDynamicSharedMemorySize,
                         FLASH_SMEM);
    cudaFuncSetAttribute(gemm_bf16x3, cudaFuncAttributeMaxDynamicSharedMemorySize,
                         GEMM_SMEM);

    init_invf<<<1, 64>>>();

    const int n4x = CM * CD / 4, n4w = CD * CD / 4;
    convert_hilo<<<dim3(n4x / 256, 1), 256>>>(X, xh, xl, X, xh, xl, X, xh, xl,
                                              X, xh, xl, n4x);
    convert_hilo<<<dim3(n4w / 256, 4), 256>>>(Wq, wqh, wql, Wk, wkh, wkl,
                                              Wv, wvh, wvl, Wo, woh, wol, n4w);

    // fused Q/K/V projections; z==2 (V) writes bf16 hi/lo planes directly
    gemm_bf16x3<<<dim3(CD / 128, CM / 128, 3), 256, GEMM_SMEM>>>(
        xh, xl, wqh, wql, wkh, wkl, wvh, wvl, qp, kp, vh, vl, 2, CD, CD);

    rope_split<<<(CM * CH * 64) / 256, 256>>>();

    flash_mma<<<dim3(CS / 128, CH, CB), 256, FLASH_SMEM>>>(mask);

    // O projection (fp32 out)
    gemm_bf16x3<<<dim3(CD / 128, CM / 128, 1), 256, GEMM_SMEM>>>(
        aoh, aol, woh, wol, woh, wol, woh, wol, out, out, nullptr, nullptr, -1, CD, CD);
}

// round 15
// speedup vs baseline: 1.1159x; 1.0051x over previous
#include <cuda_runtime.h>
#include <cuda_bf16.h>
#include <math.h>
#include <stdint.h>

#define CB 2
#define CS 2048
#define CD 2048
#define CH 16
#define CHD 128
#define CM (CB*CS)          // 4096 rows total
#define SCALE 0.08838834764831845f   // 1/sqrt(128)

// ---------------------------------------------------------------------------
// Scratch (allocation-free rule: static device globals)
// ---------------------------------------------------------------------------
__device__ float g_q[(size_t)CM * CD];
__device__ float g_k[(size_t)CM * CD];
__device__ float g_invf[64];

__device__ __nv_bfloat16 g_xh[(size_t)CM * CD];
__device__ __nv_bfloat16 g_xl[(size_t)CM * CD];
__device__ __nv_bfloat16 g_wqh[(size_t)CD * CD];
__device__ __nv_bfloat16 g_wql[(size_t)CD * CD];
__device__ __nv_bfloat16 g_wkh[(size_t)CD * CD];
__device__ __nv_bfloat16 g_wkl[(size_t)CD * CD];
__device__ __nv_bfloat16 g_wvh[(size_t)CD * CD];
__device__ __nv_bfloat16 g_wvl[(size_t)CD * CD];
__device__ __nv_bfloat16 g_woh[(size_t)CD * CD];
__device__ __nv_bfloat16 g_wol[(size_t)CD * CD];
__device__ __nv_bfloat16 g_aoh[(size_t)CM * CD];
__device__ __nv_bfloat16 g_aol[(size_t)CM * CD];

// bf16 hi/lo planes for attention inputs
__device__ __nv_bfloat16 g_qh[(size_t)CM * CD];
__device__ __nv_bfloat16 g_ql[(size_t)CM * CD];
__device__ __nv_bfloat16 g_kh[(size_t)CM * CD];
__device__ __nv_bfloat16 g_kl[(size_t)CM * CD];
__device__ __nv_bfloat16 g_vh[(size_t)CM * CD];
__device__ __nv_bfloat16 g_vl[(size_t)CM * CD];

// ---------------------------------------------------------------------------
// PTX helpers
// ---------------------------------------------------------------------------
__device__ __forceinline__ uint32_t smem_u32(const void* p) {
    return (uint32_t)__cvta_generic_to_shared(p);
}

__device__ __forceinline__ void ldsm4(uint32_t& r0, uint32_t& r1,
                                      uint32_t& r2, uint32_t& r3, uint32_t addr) {
    asm volatile("ldmatrix.sync.aligned.m8n8.x4.shared.b16 {%0,%1,%2,%3}, [%4];"
                 : "=r"(r0), "=r"(r1), "=r"(r2), "=r"(r3) : "r"(addr));
}

__device__ __forceinline__ void ldsm4t(uint32_t& r0, uint32_t& r1,
                                       uint32_t& r2, uint32_t& r3, uint32_t addr) {
    asm volatile("ldmatrix.sync.aligned.m8n8.x4.trans.shared.b16 {%0,%1,%2,%3}, [%4];"
                 : "=r"(r0), "=r"(r1), "=r"(r2), "=r"(r3) : "r"(addr));
}

__device__ __forceinline__ void mma16816(float* c, const uint32_t* a, const uint32_t* b) {
    asm volatile(
        "mma.sync.aligned.m16n8k16.row.col.f32.bf16.bf16.f32 "
        "{%0,%1,%2,%3}, {%4,%5,%6,%7}, {%8,%9}, {%0,%1,%2,%3};"
        : "+f"(c[0]), "+f"(c[1]), "+f"(c[2]), "+f"(c[3])
        : "r"(a[0]), "r"(a[1]), "r"(a[2]), "r"(a[3]), "r"(b[0]), "r"(b[1]));
}

__device__ __forceinline__ void cp16(uint32_t saddr, const void* gaddr) {
    asm volatile("cp.async.cg.shared.global [%0], [%1], 16;"
                 :: "r"(saddr), "l"(gaddr) : "memory");
}
__device__ __forceinline__ void cp_commit() {
    asm volatile("cp.async.commit_group;" ::: "memory");
}
template <int N>
__device__ __forceinline__ void cp_wait() {
    asm volatile("cp.async.wait_group %0;" :: "n"(N) : "memory");
}

// ---------------------------------------------------------------------------
__global__ void init_invf()
{
    int i = threadIdx.x;
    if (i < 64)
        g_invf[i] = (float)(1.0 / pow(10000.0, (double)(2 * i) / (double)CHD));
}

// ---------------------------------------------------------------------------
// fp32 -> (bf16 hi, bf16 lo) split conversion. 4 elements per thread.
// blockIdx.y selects among up to 4 (src, hi, lo) triples.
// ---------------------------------------------------------------------------
__global__ __launch_bounds__(256) void convert_hilo(
    const float* __restrict__ s0, __nv_bfloat16* __restrict__ h0d, __nv_bfloat16* __restrict__ l0d,
    const float* __restrict__ s1, __nv_bfloat16* __restrict__ h1d, __nv_bfloat16* __restrict__ l1d,
    const float* __restrict__ s2, __nv_bfloat16* __restrict__ h2d, __nv_bfloat16* __restrict__ l2d,
    const float* __restrict__ s3, __nv_bfloat16* __restrict__ h3d, __nv_bfloat16* __restrict__ l3d,
    int n4)
{
    const float* src = (blockIdx.y == 0) ? s0 : (blockIdx.y == 1) ? s1 :
                       (blockIdx.y == 2) ? s2 : s3;
    __nv_bfloat16* hi = (blockIdx.y == 0) ? h0d : (blockIdx.y == 1) ? h1d :
                        (blockIdx.y == 2) ? h2d : h3d;
    __nv_bfloat16* lo = (blockIdx.y == 0) ? l0d : (blockIdx.y == 1) ? l1d :
                        (blockIdx.y == 2) ? l2d : l3d;

    int i = blockIdx.x * 256 + threadIdx.x;
    if (i >= n4) return;
    float4 v = ((const float4*)src)[i];
    __nv_bfloat16 h0 = __float2bfloat16_rn(v.x);
    __nv_bfloat16 h1 = __float2bfloat16_rn(v.y);
    __nv_bfloat16 h2 = __float2bfloat16_rn(v.z);
    __nv_bfloat16 h3 = __float2bfloat16_rn(v.w);
    __nv_bfloat16 l0 = __float2bfloat16_rn(v.x - __bfloat162float(h0));
    __nv_bfloat16 l1 = __float2bfloat16_rn(v.y - __bfloat162float(h1));
    __nv_bfloat16 l2 = __float2bfloat16_rn(v.z - __bfloat162float(h2));
    __nv_bfloat16 l3 = __float2bfloat16_rn(v.w - __bfloat162float(h3));
    ((__nv_bfloat162*)hi)[2 * i]     = __nv_bfloat162(h0, h1);
    ((__nv_bfloat162*)hi)[2 * i + 1] = __nv_bfloat162(h2, h3);
    ((__nv_bfloat162*)lo)[2 * i]     = __nv_bfloat162(l0, l1);
    ((__nv_bfloat162*)lo)[2 * i + 1] = __nv_bfloat162(l2, l3);
}

// ---------------------------------------------------------------------------
// bf16-split tensor-core NT GEMM: 64x32 warp tiles, cp.async double buffer,
// single sync per k-step, 2 CTAs/SM (round-13 proven).
// C = Ah Bh^T + Ah Bl^T + Al Bh^T   (fp32 accumulate)
// ---------------------------------------------------------------------------
#define GPLANE 10240
#define GSTAGE (4 * GPLANE)
#define GEMM_SMEM (2 * GSTAGE)

__global__ __launch_bounds__(256, 2) void gemm_bf16x3(
    const __nv_bfloat16* __restrict__ Ah, const __nv_bfloat16* __restrict__ Al,
    const __nv_bfloat16* __restrict__ Bh0, const __nv_bfloat16* __restrict__ Bl0,
    const __nv_bfloat16* __restrict__ Bh1, const __nv_bfloat16* __restrict__ Bl1,
    const __nv_bfloat16* __restrict__ Bh2, const __nv_bfloat16* __restrict__ Bl2,
    float* __restrict__ C0, float* __restrict__ C1,
    __nv_bfloat16* __restrict__ Cbh, __nv_bfloat16* __restrict__ Cbl, int zbf,
    int N, int K)
{
    extern __shared__ char smg[];
    const uint32_t sb = smem_u32(smg);

    const __nv_bfloat16* Bh = (blockIdx.z == 0) ? Bh0 : (blockIdx.z == 1) ? Bh1 : Bh2;
    const __nv_bfloat16* Bl = (blockIdx.z == 0) ? Bl0 : (blockIdx.z == 1) ? Bl1 : Bl2;
    float*               C  = (blockIdx.z == 0) ? C0  : C1;

    const int tid  = threadIdx.x;
    const int lane = tid & 31;
    const int wid  = tid >> 5;
    const int wm   = wid >> 2;
    const int wn   = wid & 3;
    const int bm   = blockIdx.y << 7;
    const int bn   = blockIdx.x << 7;

    const int crow0 = tid >> 2,        cc0 = tid & 3;
    const int crow1 = 64 + (tid >> 2), cc1 = tid & 3;
    const uint32_t so0 = crow0 * 80 + cc0 * 16;
    const uint32_t so1 = crow1 * 80 + cc1 * 16;
    const size_t gA0 = (size_t)(bm + crow0) * K + cc0 * 8;
    const size_t gA1 = (size_t)(bm + crow1) * K + cc1 * 8;
    const size_t gB0 = (size_t)(bn + crow0) * K + cc0 * 8;
    const size_t gB1 = (size_t)(bn + crow1) * K + cc1 * 8;

    float acc[4][4][4];
#pragma unroll
    for (int i = 0; i < 4; i++)
#pragma unroll
        for (int j = 0; j < 4; j++)
#pragma unroll
            for (int r = 0; r < 4; r++) acc[i][j][r] = 0.f;

    const int a_row = wm * 64 + (lane & 15);
    const int a_ch  = lane >> 4;
    const int b_row = wn * 32 + (lane & 7) + ((lane >> 4) << 3);
    const int b_ch  = (lane >> 3) & 1;

    const int iters = K >> 5;

    auto issue = [&](int ki) {
        const uint32_t sa = sb + (ki & 1) * GSTAGE;
        const int k0 = ki << 5;
        cp16(sa + so0,              Ah + gA0 + k0);
        cp16(sa + so1,              Ah + gA1 + k0);
        cp16(sa + GPLANE + so0,     Al + gA0 + k0);
        cp16(sa + GPLANE + so1,     Al + gA1 + k0);
        cp16(sa + 2 * GPLANE + so0, Bh + gB0 + k0);
        cp16(sa + 2 * GPLANE + so1, Bh + gB1 + k0);
        cp16(sa + 3 * GPLANE + so0, Bl + gB0 + k0);
        cp16(sa + 3 * GPLANE + so1, Bl + gB1 + k0);
        cp_commit();
    };

    issue(0);

    for (int it = 0; it < iters; it++) {
        cp_wait<0>();
        __syncthreads();

        if (it + 1 < iters) issue(it + 1);

        const uint32_t stage = sb + (it & 1) * GSTAGE;

#pragma unroll
        for (int kh = 0; kh < 2; kh++) {
            uint32_t ah[4][4], al[4][4], bh[4][2], bl[4][2];
#pragma unroll
            for (int mt = 0; mt < 4; mt++) {
                uint32_t addr = stage + (a_row + mt * 16) * 80 + (2 * kh + a_ch) * 16;
                ldsm4(ah[mt][0], ah[mt][1], ah[mt][2], ah[mt][3], addr);
                ldsm4(al[mt][0], al[mt][1], al[mt][2], al[mt][3], addr + GPLANE);
            }
#pragma unroll
            for (int nt = 0; nt < 2; nt++) {
                uint32_t addr = stage + 2 * GPLANE +
                                (b_row + nt * 16) * 80 + (2 * kh + b_ch) * 16;
                ldsm4(bh[nt * 2][0], bh[nt * 2][1],
                      bh[nt * 2 + 1][0], bh[nt * 2 + 1][1], addr);
                ldsm4(bl[nt * 2][0], bl[nt * 2][1],
                      bl[nt * 2 + 1][0], bl[nt * 2 + 1][1], addr + GPLANE);
            }
#pragma unroll
            for (int mt = 0; mt < 4; mt++)
#pragma unroll
                for (int n8 = 0; n8 < 4; n8++) {
                    mma16816(acc[mt][n8], ah[mt], bh[n8]);
                    mma16816(acc[mt][n8], ah[mt], bl[n8]);
                    mma16816(acc[mt][n8], al[mt], bh[n8]);
                }
        }
    }

    if ((int)blockIdx.z == zbf) {
#pragma unroll
        for (int mt = 0; mt < 4; mt++) {
            const int gm = bm + wm * 64 + mt * 16 + (lane >> 2);
#pragma unroll
            for (int n8 = 0; n8 < 4; n8++) {
                const int gc = bn + wn * 32 + n8 * 8 + ((lane & 3) << 1);
#pragma unroll
                for (int hrow = 0; hrow < 2; hrow++) {
                    float o0 = acc[mt][n8][hrow * 2];
                    float o1 = acc[mt][n8][hrow * 2 + 1];
                    size_t off = (size_t)(gm + hrow * 8) * N + gc;
                    __nv_bfloat16 h0 = __float2bfloat16_rn(o0);
                    __nv_bfloat16 h1 = __float2bfloat16_rn(o1);
                    __nv_bfloat162 hv(h0, h1);
                    __nv_bfloat162 lv(__float2bfloat16_rn(o0 - __bfloat162float(h0)),
                                      __float2bfloat16_rn(o1 - __bfloat162float(h1)));
                    *(uint32_t*)(&Cbh[off]) = *(uint32_t*)&hv;
                    *(uint32_t*)(&Cbl[off]) = *(uint32_t*)&lv;
                }
            }
        }
    } else {
#pragma unroll
        for (int mt = 0; mt < 4; mt++) {
            const int gm = bm + wm * 64 + mt * 16 + (lane >> 2);
#pragma unroll
            for (int n8 = 0; n8 < 4; n8++) {
                const int gc = bn + wn * 32 + n8 * 8 + ((lane & 3) << 1);
                *(float2*)(&C[(size_t)gm * N + gc]) =
                    make_float2(acc[mt][n8][0], acc[mt][n8][1]);
                *(float2*)(&C[(size_t)(gm + 8) * N + gc]) =
                    make_float2(acc[mt][n8][2], acc[mt][n8][3]);
            }
        }
    }
}

// ---------------------------------------------------------------------------
// RoPE: reads fp32 g_q/g_k, writes bf16 hi/lo planes qh/ql/kh/kl.
// ---------------------------------------------------------------------------
__global__ __launch_bounds__(256) void rope_split()
{
    int idx = blockIdx.x * 256 + threadIdx.x;
    int i = idx & 63;
    int m = idx >> 10;
    int s = m & (CS - 1);

    float inv = g_invf[i];
    float ang = (float)s * inv;
    float c, sn;
    sincosf(ang, &sn, &c);

    int h = (idx >> 6) & (CH - 1);
    size_t base = (size_t)m * CD + (size_t)h * CHD;

    float q1 = g_q[base + i], q2 = g_q[base + i + 64];
    float rq1 = q1 * c - q2 * sn;
    float rq2 = q2 * c + q1 * sn;
    float k1 = g_k[base + i], k2 = g_k[base + i + 64];
    float rk1 = k1 * c - k2 * sn;
    float rk2 = k2 * c + k1 * sn;

    __nv_bfloat16 h1 = __float2bfloat16_rn(rq1);
    __nv_bfloat16 h2 = __float2bfloat16_rn(rq2);
    g_qh[base + i]      = h1;
    g_qh[base + i + 64] = h2;
    g_ql[base + i]      = __float2bfloat16_rn(rq1 - __bfloat162float(h1));
    g_ql[base + i + 64] = __float2bfloat16_rn(rq2 - __bfloat162float(h2));

    __nv_bfloat16 h3 = __float2bfloat16_rn(rk1);
    __nv_bfloat16 h4 = __float2bfloat16_rn(rk2);
    g_kh[base + i]      = h3;
    g_kh[base + i + 64] = h4;
    g_kl[base + i]      = __float2bfloat16_rn(rk1 - __bfloat162float(h3));
    g_kl[base + i + 64] = __float2bfloat16_rn(rk2 - __bfloat162float(h4));
}

// ---------------------------------------------------------------------------
// Flash attention, FA2-style with Q fragments register-resident.
// Warp owns 16 full rows; softmax + P in registers; pipelined 64-col k-tiles
// with 3-slot K/V cp.async ring. Q loaded to fragments once before mainloop.
// smem: Q planes (2x34816) + 3 KV slots (3x34816) = 174080 B.
// ---------------------------------------------------------------------------
#define FOFF_QH  0
#define FOFF_QL  34816
#define FOFF_KV  69632
#define KVSLOT   34816          // 64 rows x 272B x 2 planes (h @0, l @17408)
#define FLASH_SMEM 174080

__global__ __launch_bounds__(256, 1) void flash_mma(const float* __restrict__ mask)
{
    extern __shared__ char smc[];

    const int tid  = threadIdx.x;
    const int lane = tid & 31;
    const int wid  = tid >> 5;      // 0..7: warp owns rows wid*16..wid*16+15
    const int b    = blockIdx.z;
    const int h    = blockIdx.y;
    const int q0   = blockIdx.x << 7;

    const __nv_bfloat16* Qhg = g_qh + (size_t)(b * CS + q0) * CD + (size_t)h * CHD;
    const __nv_bfloat16* Qlg = g_ql + (size_t)(b * CS + q0) * CD + (size_t)h * CHD;
    const __nv_bfloat16* Khg = g_kh + (size_t)(b * CS) * CD + (size_t)h * CHD;
    const __nv_bfloat16* Klg = g_kl + (size_t)(b * CS) * CD + (size_t)h * CHD;
    const __nv_bfloat16* Vhg = g_vh + (size_t)(b * CS) * CD + (size_t)h * CHD;
    const __nv_bfloat16* Vlg = g_vl + (size_t)(b * CS) * CD + (size_t)h * CHD;

    const uint32_t sQ_u  = smem_u32(smc) + FOFF_QH;
    const uint32_t sKV_u = smem_u32(smc) + FOFF_KV;

    auto issueK = [&](int t) {
        if (t < 32) {
            const uint32_t buf = sKV_u + ((2 * t) % 3) * KVSLOT;
            const int k0 = t << 6;
            for (int i = tid; i < 1024; i += 256) {
                int r = i >> 4, c = i & 15;
                cp16(buf + r * 272 + c * 16,
                     Khg + (size_t)(k0 + r) * CD + c * 8);
                cp16(buf + 17408 + r * 272 + c * 16,
                     Klg + (size_t)(k0 + r) * CD + c * 8);
            }
        }
        cp_commit();
    };
    auto issueV = [&](int t) {
        if (t < 32) {
            const uint32_t buf = sKV_u + ((2 * t + 1) % 3) * KVSLOT;
            const int k0 = t << 6;
            for (int i = tid; i < 1024; i += 256) {
                int r = i >> 4, c = i & 15;
                cp16(buf + r * 272 + c * 16,
                     Vhg + (size_t)(k0 + r) * CD + c * 8);
                cp16(buf + 17408 + r * 272 + c * 16,
                     Vlg + (size_t)(k0 + r) * CD + c * 8);
            }
        }
        cp_commit();
    };

    // prologue: Q, K0, V0
    for (int i = tid; i < 2048; i += 256) {
        int r = i >> 4, c = i & 15;
        cp16(sQ_u + r * 272 + c * 16,         Qhg + (size_t)r * CD + c * 8);
        cp16(sQ_u + 34816 + r * 272 + c * 16, Qlg + (size_t)r * CD + c * 8);
    }
    cp_commit();
    issueK(0);
    issueV(0);

    // lane address components (proven formulas, warp tile = 16 rows)
    const int a_r   = wid * 16 + (lane & 15);
    const int a_c   = lane >> 4;
    const int b_r16 = (lane & 7) + ((lane >> 4) << 3);
    const int b_c   = (lane >> 3) & 1;
    const int v_key = ((lane >> 3) & 1) * 8 + (lane & 7);
    const int v_cg  = (lane >> 4) << 3;
    const int row0  = wid * 16 + (lane >> 2);
    const int colb  = (lane & 3) << 1;

    // hoist Q fragments into registers (Q group drained; K0/V0 may pend)
    cp_wait<2>();
    __syncthreads();
    uint32_t qh_f[8][4], ql_f[8][4];
#pragma unroll
    for (int tt = 0; tt < 8; tt++) {
        uint32_t addr = sQ_u + a_r * 272 + (tt * 2 + a_c) * 16;
        ldsm4(qh_f[tt][0], qh_f[tt][1], qh_f[tt][2], qh_f[tt][3], addr);
        ldsm4(ql_f[tt][0], ql_f[tt][1], ql_f[tt][2], ql_f[tt][3], addr + 34816);
    }

    // per-thread state: two rows (r0 = wid*16 + lane/4, r1 = r0 + 8)
    float m_pr0 = -INFINITY, m_pr1 = -INFINITY;
    float l_pr0 = 0.f,       l_pr1 = 0.f;
    float oacc[16][4];
#pragma unroll
    for (int i = 0; i < 16; i++)
#pragma unroll
        for (int r = 0; r < 4; r++) oacc[i][r] = 0.f;

    const float* mrow0 = mask + ((size_t)b * CS + (q0 + row0)) * CS;
    const float* mrow1 = mrow0 + (size_t)8 * CS;

    for (int t = 0; t < 32; t++) {
        const int k0 = t << 6;
        // K(t) resident; all warps past PV(t-1)
        cp_wait<1>();
        __syncthreads();
        issueK(t + 1);   // into V(t-1)'s slot

        const uint32_t kbuf = sKV_u + ((2 * t) % 3) * KVSLOT;
        const uint32_t vbuf = sKV_u + ((2 * t + 1) % 3) * KVSLOT;

        // prefetch mask values for this tile into registers (hidden under MMA)
        float2 mr0[8], mr1[8];
#pragma unroll
        for (int n8 = 0; n8 < 8; n8++) {
            mr0[n8] = *(const float2*)(mrow0 + k0 + n8 * 8 + colb);
            mr1[n8] = *(const float2*)(mrow1 + k0 + n8 * 8 + colb);
        }

        // ---- S = Q K^T (bf16x3): warp computes 16 rows x 64 cols ----
        float sacc[8][4];
#pragma unroll
        for (int i = 0; i < 8; i++)
#pragma unroll
            for (int r = 0; r < 4; r++) sacc[i][r] = 0.f;

#pragma unroll
        for (int tt = 0; tt < 8; tt++) {
            uint32_t bh[8][2], bl[8][2];
#pragma unroll
            for (int g = 0; g < 4; g++) {
                uint32_t addr = kbuf + (g * 16 + b_r16) * 272 + (tt * 2 + b_c) * 16;
                ldsm4(bh[2*g][0], bh[2*g][1], bh[2*g+1][0], bh[2*g+1][1], addr);
                ldsm4(bl[2*g][0], bl[2*g][1], bl[2*g+1][0], bl[2*g+1][1], addr + 17408);
            }
#pragma unroll
            for (int n8 = 0; n8 < 8; n8++) {
                mma16816(sacc[n8], qh_f[tt], bh[n8]);
                mma16816(sacc[n8], qh_f[tt], bl[n8]);
                mma16816(sacc[n8], ql_f[tt], bh[n8]);
            }
        }
        __syncthreads();   // all warps done reading K(t) slot
        issueV(t + 1);     // into K(t)'s slot

        // ---- register softmax (rows r0, r1 private to this lane group) ----
        float mx0 = -INFINITY, mx1 = -INFINITY;
#pragma unroll
        for (int n8 = 0; n8 < 8; n8++) {
            sacc[n8][0] = sacc[n8][0] * SCALE + mr0[n8].x;
            sacc[n8][1] = sacc[n8][1] * SCALE + mr0[n8].y;
            sacc[n8][2] = sacc[n8][2] * SCALE + mr1[n8].x;
            sacc[n8][3] = sacc[n8][3] * SCALE + mr1[n8].y;
            mx0 = fmaxf(mx0, fmaxf(sacc[n8][0], sacc[n8][1]));
            mx1 = fmaxf(mx1, fmaxf(sacc[n8][2], sacc[n8][3]));
        }
        mx0 = fmaxf(mx0, __shfl_xor_sync(0xffffffffu, mx0, 1));
        mx0 = fmaxf(mx0, __shfl_xor_sync(0xffffffffu, mx0, 2));
        mx1 = fmaxf(mx1, __shfl_xor_sync(0xffffffffu, mx1, 1));
        mx1 = fmaxf(mx1, __shfl_xor_sync(0xffffffffu, mx1, 2));
        mx0 = fmaxf(mx0, m_pr0);
        mx1 = fmaxf(mx1, m_pr1);
        const float al0 = __expf(m_pr0 - mx0);
        const float al1 = __expf(m_pr1 - mx1);

        float sum0 = 0.f, sum1 = 0.f;
        uint32_t ph0[8], ph1[8], pl0[8], pl1[8];
#pragma unroll
        for (int n8 = 0; n8 < 8; n8++) {
            float p0 = __expf(sacc[n8][0] - mx0);
            float p1 = __expf(sacc[n8][1] - mx0);
            float p2 = __expf(sacc[n8][2] - mx1);
            float p3 = __expf(sacc[n8][3] - mx1);
            sum0 += p0 + p1;
            sum1 += p2 + p3;
            __nv_bfloat16 h0 = __float2bfloat16_rn(p0);
            __nv_bfloat16 h1 = __float2bfloat16_rn(p1);
            __nv_bfloat16 h2 = __float2bfloat16_rn(p2);
            __nv_bfloat16 h3 = __float2bfloat16_rn(p3);
            __nv_bfloat162 hv0(h0, h1), hv1(h2, h3);
            __nv_bfloat162 lv0(__float2bfloat16_rn(p0 - __bfloat162float(h0)),
                               __float2bfloat16_rn(p1 - __bfloat162float(h1)));
            __nv_bfloat162 lv1(__float2bfloat16_rn(p2 - __bfloat162float(h2)),
                               __float2bfloat16_rn(p3 - __bfloat162float(h3)));
            ph0[n8] = *(uint32_t*)&hv0;
            ph1[n8] = *(uint32_t*)&hv1;
            pl0[n8] = *(uint32_t*)&lv0;
            pl1[n8] = *(uint32_t*)&lv1;
        }
        sum0 += __shfl_xor_sync(0xffffffffu, sum0, 1);
        sum0 += __shfl_xor_sync(0xffffffffu, sum0, 2);
        sum1 += __shfl_xor_sync(0xffffffffu, sum1, 1);
        sum1 += __shfl_xor_sync(0xffffffffu, sum1, 2);
        l_pr0 = l_pr0 * al0 + sum0;
        l_pr1 = l_pr1 * al1 + sum1;
        m_pr0 = mx0;
        m_pr1 = mx1;

        // rescale output accumulator
#pragma unroll
        for (int n8 = 0; n8 < 16; n8++) {
            oacc[n8][0] *= al0;
            oacc[n8][1] *= al0;
            oacc[n8][2] *= al1;
            oacc[n8][3] *= al1;
        }

        cp_wait<2>();      // V(t) resident (K(t+1), V(t+1) in flight)
        __syncthreads();   // V(t) writes visible to all warps

        // ---- O += P V (bf16x3): A-frags straight from P registers ----
#pragma unroll
        for (int kt = 0; kt < 4; kt++) {
            uint32_t paH[4] = { ph0[2*kt], ph1[2*kt], ph0[2*kt+1], ph1[2*kt+1] };
            uint32_t paL[4] = { pl0[2*kt], pl1[2*kt], pl0[2*kt+1], pl1[2*kt+1] };
#pragma unroll
            for (int g = 0; g < 8; g++) {
                uint32_t vh[4], vl[4];
                uint32_t addr = vbuf + (kt * 16 + v_key) * 272 + (g * 16 + v_cg) * 2;
                ldsm4t(vh[0], vh[1], vh[2], vh[3], addr);
                ldsm4t(vl[0], vl[1], vl[2], vl[3], addr + 17408);
                uint32_t bH0[2] = { vh[0], vh[1] }, bL0[2] = { vl[0], vl[1] };
                uint32_t bH1[2] = { vh[2], vh[3] }, bL1[2] = { vl[2], vl[3] };
                mma16816(oacc[2*g],     paH, bH0);
                mma16816(oacc[2*g],     paH, bL0);
                mma16816(oacc[2*g],     paL, bH0);
                mma16816(oacc[2*g+1],   paH, bH1);
                mma16816(oacc[2*g+1],   paH, bL1);
                mma16816(oacc[2*g+1],   paL, bH1);
            }
        }
    }

    // epilogue: /l, bf16 hi/lo split store (rows row0, row0+8)
    const float inv0 = 1.0f / l_pr0;
    const float inv1 = 1.0f / l_pr1;
#pragma unroll
    for (int n8 = 0; n8 < 16; n8++) {
        const int cc = n8 * 8 + colb;
#pragma unroll
        for (int hrow = 0; hrow < 2; hrow++) {
            float o0 = oacc[n8][hrow * 2]     * (hrow ? inv1 : inv0);
            float o1 = oacc[n8][hrow * 2 + 1] * (hrow ? inv1 : inv0);
            size_t off = (size_t)(b * CS + q0 + row0 + hrow * 8) * CD
                       + (size_t)h * CHD + cc;
            __nv_bfloat16 h0 = __float2bfloat16_rn(o0);
            __nv_bfloat16 h1 = __float2bfloat16_rn(o1);
            __nv_bfloat162 hv(h0, h1);
            __nv_bfloat162 lv(__float2bfloat16_rn(o0 - __bfloat162float(h0)),
                              __float2bfloat16_rn(o1 - __bfloat162float(h1)));
            *(uint32_t*)(&g_aoh[off]) = *(uint32_t*)&hv;
            *(uint32_t*)(&g_aol[off]) = *(uint32_t*)&lv;
        }
    }
}

// ---------------------------------------------------------------------------
extern "C" void kernel_launch(void* const* d_in, const int* in_sizes, int n_in,
                              void* d_out, int out_size)
{
    const float* X    = (const float*)d_in[0];
    const float* mask = (const float*)d_in[1];
    const float* Wq   = (const float*)d_in[2];
    const float* Wk   = (const float*)d_in[3];
    const float* Wv   = (const float*)d_in[4];
    const float* Wo   = (const float*)d_in[5];
    float* out = (float*)d_out;

    float *qp, *kp;
    cudaGetSymbolAddress((void**)&qp, g_q);
    cudaGetSymbolAddress((void**)&kp, g_k);
    __nv_bfloat16 *xh, *xl, *wqh, *wql, *wkh, *wkl, *wvh, *wvl, *woh, *wol, *aoh, *aol;
    __nv_bfloat16 *vh, *vl;
    cudaGetSymbolAddress((void**)&xh,  g_xh);
    cudaGetSymbolAddress((void**)&xl,  g_xl);
    cudaGetSymbolAddress((void**)&wqh, g_wqh);
    cudaGetSymbolAddress((void**)&wql, g_wql);
    cudaGetSymbolAddress((void**)&wkh, g_wkh);
    cudaGetSymbolAddress((void**)&wkl, g_wkl);
    cudaGetSymbolAddress((void**)&wvh, g_wvh);
    cudaGetSymbolAddress((void**)&wvl, g_wvl);
    cudaGetSymbolAddress((void**)&woh, g_woh);
    cudaGetSymbolAddress((void**)&wol, g_wol);
    cudaGetSymbolAddress((void**)&aoh, g_aoh);
    cudaGetSymbolAddress((void**)&aol, g_aol);
    cudaGetSymbolAddress((void**)&vh,  g_vh);
    cudaGetSymbolAddress((void**)&vl,  g_vl);

    cudaFuncSetAttribute(flash_mma, cudaFuncAttributeMaxDynamicSharedMemorySize,
                         FLASH_SMEM);
    cudaFuncSetAttribute(gemm_bf16x3, cudaFuncAttributeMaxDynamicSharedMemorySize,
                         GEMM_SMEM);

    init_invf<<<1, 64>>>();

    const int n4x = CM * CD / 4, n4w = CD * CD / 4;
    convert_hilo<<<dim3(n4x / 256, 1), 256>>>(X, xh, xl, X, xh, xl, X, xh, xl,
                                              X, xh, xl, n4x);
    convert_hilo<<<dim3(n4w / 256, 4), 256>>>(Wq, wqh, wql, Wk, wkh, wkl,
                                              Wv, wvh, wvl, Wo, woh, wol, n4w);

    // fused Q/K/V projections; z==2 (V) writes bf16 hi/lo planes directly
    gemm_bf16x3<<<dim3(CD / 128, CM / 128, 3), 256, GEMM_SMEM>>>(
        xh, xl, wqh, wql, wkh, wkl, wvh, wvl, qp, kp, vh, vl, 2, CD, CD);

    rope_split<<<(CM * CH * 64) / 256, 256>>>();

    flash_mma<<<dim3(CS / 128, CH, CB), 256, FLASH_SMEM>>>(mask);

    // O projection (fp32 out)
    gemm_bf16x3<<<dim3(CD / 128, CM / 128, 1), 256, GEMM_SMEM>>>(
        aoh, aol, woh, wol, woh, wol, woh, wol, out, out, nullptr, nullptr, -1, CD, CD);
}

// round 17
// speedup vs baseline: 1.1725x; 1.0507x over previous
#include <cuda_runtime.h>
#include <cuda_bf16.h>
#include <math.h>
#include <stdint.h>

#define CB 2
#define CS 2048
#define CD 2048
#define CH 16
#define CHD 128
#define CM (CB*CS)          // 4096 rows total
#define SCALE 0.08838834764831845f   // 1/sqrt(128)

// ---------------------------------------------------------------------------
// Scratch (allocation-free rule: static device globals)
// ---------------------------------------------------------------------------
__device__ float g_q[(size_t)CM * CD];
__device__ float g_k[(size_t)CM * CD];
__device__ float g_invf[64];

__device__ __nv_bfloat16 g_xh[(size_t)CM * CD];
__device__ __nv_bfloat16 g_xl[(size_t)CM * CD];
__device__ __nv_bfloat16 g_wqh[(size_t)CD * CD];
__device__ __nv_bfloat16 g_wql[(size_t)CD * CD];
__device__ __nv_bfloat16 g_wkh[(size_t)CD * CD];
__device__ __nv_bfloat16 g_wkl[(size_t)CD * CD];
__device__ __nv_bfloat16 g_wvh[(size_t)CD * CD];
__device__ __nv_bfloat16 g_wvl[(size_t)CD * CD];
__device__ __nv_bfloat16 g_woh[(size_t)CD * CD];
__device__ __nv_bfloat16 g_wol[(size_t)CD * CD];
__device__ __nv_bfloat16 g_aoh[(size_t)CM * CD];
__device__ __nv_bfloat16 g_aol[(size_t)CM * CD];

// bf16 hi/lo planes for attention inputs
__device__ __nv_bfloat16 g_qh[(size_t)CM * CD];
__device__ __nv_bfloat16 g_ql[(size_t)CM * CD];
__device__ __nv_bfloat16 g_kh[(size_t)CM * CD];
__device__ __nv_bfloat16 g_kl[(size_t)CM * CD];
__device__ __nv_bfloat16 g_vh[(size_t)CM * CD];
__device__ __nv_bfloat16 g_vl[(size_t)CM * CD];

// ---------------------------------------------------------------------------
// PTX helpers
// ---------------------------------------------------------------------------
__device__ __forceinline__ uint32_t smem_u32(const void* p) {
    return (uint32_t)__cvta_generic_to_shared(p);
}

__device__ __forceinline__ void ldsm4(uint32_t& r0, uint32_t& r1,
                                      uint32_t& r2, uint32_t& r3, uint32_t addr) {
    asm volatile("ldmatrix.sync.aligned.m8n8.x4.shared.b16 {%0,%1,%2,%3}, [%4];"
                 : "=r"(r0), "=r"(r1), "=r"(r2), "=r"(r3) : "r"(addr));
}

__device__ __forceinline__ void ldsm4t(uint32_t& r0, uint32_t& r1,
                                       uint32_t& r2, uint32_t& r3, uint32_t addr) {
    asm volatile("ldmatrix.sync.aligned.m8n8.x4.trans.shared.b16 {%0,%1,%2,%3}, [%4];"
                 : "=r"(r0), "=r"(r1), "=r"(r2), "=r"(r3) : "r"(addr));
}

__device__ __forceinline__ void mma16816(float* c, const uint32_t* a, const uint32_t* b) {
    asm volatile(
        "mma.sync.aligned.m16n8k16.row.col.f32.bf16.bf16.f32 "
        "{%0,%1,%2,%3}, {%4,%5,%6,%7}, {%8,%9}, {%0,%1,%2,%3};"
        : "+f"(c[0]), "+f"(c[1]), "+f"(c[2]), "+f"(c[3])
        : "r"(a[0]), "r"(a[1]), "r"(a[2]), "r"(a[3]), "r"(b[0]), "r"(b[1]));
}

__device__ __forceinline__ void cp16(uint32_t saddr, const void* gaddr) {
    asm volatile("cp.async.cg.shared.global [%0], [%1], 16;"
                 :: "r"(saddr), "l"(gaddr) : "memory");
}
__device__ __forceinline__ void cp_commit() {
    asm volatile("cp.async.commit_group;" ::: "memory");
}
template <int N>
__device__ __forceinline__ void cp_wait() {
    asm volatile("cp.async.wait_group %0;" :: "n"(N) : "memory");
}

// ---------------------------------------------------------------------------
__global__ void init_invf()
{
    int i = threadIdx.x;
    if (i < 64)
        g_invf[i] = (float)(1.0 / pow(10000.0, (double)(2 * i) / (double)CHD));
}

// ---------------------------------------------------------------------------
// fp32 -> (bf16 hi, bf16 lo) split conversion. 4 elements per thread.
// blockIdx.y selects among up to 4 (src, hi, lo) triples.
// ---------------------------------------------------------------------------
__global__ __launch_bounds__(256) void convert_hilo(
    const float* __restrict__ s0, __nv_bfloat16* __restrict__ h0d, __nv_bfloat16* __restrict__ l0d,
    const float* __restrict__ s1, __nv_bfloat16* __restrict__ h1d, __nv_bfloat16* __restrict__ l1d,
    const float* __restrict__ s2, __nv_bfloat16* __restrict__ h2d, __nv_bfloat16* __restrict__ l2d,
    const float* __restrict__ s3, __nv_bfloat16* __restrict__ h3d, __nv_bfloat16* __restrict__ l3d,
    int n4)
{
    const float* src = (blockIdx.y == 0) ? s0 : (blockIdx.y == 1) ? s1 :
                       (blockIdx.y == 2) ? s2 : s3;
    __nv_bfloat16* hi = (blockIdx.y == 0) ? h0d : (blockIdx.y == 1) ? h1d :
                        (blockIdx.y == 2) ? h2d : h3d;
    __nv_bfloat16* lo = (blockIdx.y == 0) ? l0d : (blockIdx.y == 1) ? l1d :
                        (blockIdx.y == 2) ? l2d : l3d;

    int i = blockIdx.x * 256 + threadIdx.x;
    if (i >= n4) return;
    float4 v = ((const float4*)src)[i];
    __nv_bfloat16 h0 = __float2bfloat16_rn(v.x);
    __nv_bfloat16 h1 = __float2bfloat16_rn(v.y);
    __nv_bfloat16 h2 = __float2bfloat16_rn(v.z);
    __nv_bfloat16 h3 = __float2bfloat16_rn(v.w);
    __nv_bfloat16 l0 = __float2bfloat16_rn(v.x - __bfloat162float(h0));
    __nv_bfloat16 l1 = __float2bfloat16_rn(v.y - __bfloat162float(h1));
    __nv_bfloat16 l2 = __float2bfloat16_rn(v.z - __bfloat162float(h2));
    __nv_bfloat16 l3 = __float2bfloat16_rn(v.w - __bfloat162float(h3));
    ((__nv_bfloat162*)hi)[2 * i]     = __nv_bfloat162(h0, h1);
    ((__nv_bfloat162*)hi)[2 * i + 1] = __nv_bfloat162(h2, h3);
    ((__nv_bfloat162*)lo)[2 * i]     = __nv_bfloat162(l0, l1);
    ((__nv_bfloat162*)lo)[2 * i + 1] = __nv_bfloat162(l2, l3);
}

// ---------------------------------------------------------------------------
// bf16-split tensor-core NT GEMM: 64x32 warp tiles, cp.async double buffer,
// single sync per k-step, 2 CTAs/SM (round-13 proven).
// C = Ah Bh^T + Ah Bl^T + Al Bh^T   (fp32 accumulate)
// ---------------------------------------------------------------------------
#define GPLANE 10240
#define GSTAGE (4 * GPLANE)
#define GEMM_SMEM (2 * GSTAGE)

__global__ __launch_bounds__(256, 2) void gemm_bf16x3(
    const __nv_bfloat16* __restrict__ Ah, const __nv_bfloat16* __restrict__ Al,
    const __nv_bfloat16* __restrict__ Bh0, const __nv_bfloat16* __restrict__ Bl0,
    const __nv_bfloat16* __restrict__ Bh1, const __nv_bfloat16* __restrict__ Bl1,
    const __nv_bfloat16* __restrict__ Bh2, const __nv_bfloat16* __restrict__ Bl2,
    float* __restrict__ C0, float* __restrict__ C1,
    __nv_bfloat16* __restrict__ Cbh, __nv_bfloat16* __restrict__ Cbl, int zbf,
    int N, int K)
{
    extern __shared__ char smg[];
    const uint32_t sb = smem_u32(smg);

    const __nv_bfloat16* Bh = (blockIdx.z == 0) ? Bh0 : (blockIdx.z == 1) ? Bh1 : Bh2;
    const __nv_bfloat16* Bl = (blockIdx.z == 0) ? Bl0 : (blockIdx.z == 1) ? Bl1 : Bl2;
    float*               C  = (blockIdx.z == 0) ? C0  : C1;

    const int tid  = threadIdx.x;
    const int lane = tid & 31;
    const int wid  = tid >> 5;
    const int wm   = wid >> 2;
    const int wn   = wid & 3;
    const int bm   = blockIdx.y << 7;
    const int bn   = blockIdx.x << 7;

    const int crow0 = tid >> 2,        cc0 = tid & 3;
    const int crow1 = 64 + (tid >> 2), cc1 = tid & 3;
    const uint32_t so0 = crow0 * 80 + cc0 * 16;
    const uint32_t so1 = crow1 * 80 + cc1 * 16;
    const size_t gA0 = (size_t)(bm + crow0) * K + cc0 * 8;
    const size_t gA1 = (size_t)(bm + crow1) * K + cc1 * 8;
    const size_t gB0 = (size_t)(bn + crow0) * K + cc0 * 8;
    const size_t gB1 = (size_t)(bn + crow1) * K + cc1 * 8;

    float acc[4][4][4];
#pragma unroll
    for (int i = 0; i < 4; i++)
#pragma unroll
        for (int j = 0; j < 4; j++)
#pragma unroll
            for (int r = 0; r < 4; r++) acc[i][j][r] = 0.f;

    const int a_row = wm * 64 + (lane & 15);
    const int a_ch  = lane >> 4;
    const int b_row = wn * 32 + (lane & 7) + ((lane >> 4) << 3);
    const int b_ch  = (lane >> 3) & 1;

    const int iters = K >> 5;

    auto issue = [&](int ki) {
        const uint32_t sa = sb + (ki & 1) * GSTAGE;
        const int k0 = ki << 5;
        cp16(sa + so0,              Ah + gA0 + k0);
        cp16(sa + so1,              Ah + gA1 + k0);
        cp16(sa + GPLANE + so0,     Al + gA0 + k0);
        cp16(sa + GPLANE + so1,     Al + gA1 + k0);
        cp16(sa + 2 * GPLANE + so0, Bh + gB0 + k0);
        cp16(sa + 2 * GPLANE + so1, Bh + gB1 + k0);
        cp16(sa + 3 * GPLANE + so0, Bl + gB0 + k0);
        cp16(sa + 3 * GPLANE + so1, Bl + gB1 + k0);
        cp_commit();
    };

    issue(0);

    for (int it = 0; it < iters; it++) {
        cp_wait<0>();
        __syncthreads();

        if (it + 1 < iters) issue(it + 1);

        const uint32_t stage = sb + (it & 1) * GSTAGE;

#pragma unroll
        for (int kh = 0; kh < 2; kh++) {
            uint32_t ah[4][4], al[4][4], bh[4][2], bl[4][2];
#pragma unroll
            for (int mt = 0; mt < 4; mt++) {
                uint32_t addr = stage + (a_row + mt * 16) * 80 + (2 * kh + a_ch) * 16;
                ldsm4(ah[mt][0], ah[mt][1], ah[mt][2], ah[mt][3], addr);
                ldsm4(al[mt][0], al[mt][1], al[mt][2], al[mt][3], addr + GPLANE);
            }
#pragma unroll
            for (int nt = 0; nt < 2; nt++) {
                uint32_t addr = stage + 2 * GPLANE +
                                (b_row + nt * 16) * 80 + (2 * kh + b_ch) * 16;
                ldsm4(bh[nt * 2][0], bh[nt * 2][1],
                      bh[nt * 2 + 1][0], bh[nt * 2 + 1][1], addr);
                ldsm4(bl[nt * 2][0], bl[nt * 2][1],
                      bl[nt * 2 + 1][0], bl[nt * 2 + 1][1], addr + GPLANE);
            }
#pragma unroll
            for (int mt = 0; mt < 4; mt++)
#pragma unroll
                for (int n8 = 0; n8 < 4; n8++) {
                    mma16816(acc[mt][n8], ah[mt], bh[n8]);
                    mma16816(acc[mt][n8], ah[mt], bl[n8]);
                    mma16816(acc[mt][n8], al[mt], bh[n8]);
                }
        }
    }

    if ((int)blockIdx.z == zbf) {
#pragma unroll
        for (int mt = 0; mt < 4; mt++) {
            const int gm = bm + wm * 64 + mt * 16 + (lane >> 2);
#pragma unroll
            for (int n8 = 0; n8 < 4; n8++) {
                const int gc = bn + wn * 32 + n8 * 8 + ((lane & 3) << 1);
#pragma unroll
                for (int hrow = 0; hrow < 2; hrow++) {
                    float o0 = acc[mt][n8][hrow * 2];
                    float o1 = acc[mt][n8][hrow * 2 + 1];
                    size_t off = (size_t)(gm + hrow * 8) * N + gc;
                    __nv_bfloat16 h0 = __float2bfloat16_rn(o0);
                    __nv_bfloat16 h1 = __float2bfloat16_rn(o1);
                    __nv_bfloat162 hv(h0, h1);
                    __nv_bfloat162 lv(__float2bfloat16_rn(o0 - __bfloat162float(h0)),
                                      __float2bfloat16_rn(o1 - __bfloat162float(h1)));
                    *(uint32_t*)(&Cbh[off]) = *(uint32_t*)&hv;
                    *(uint32_t*)(&Cbl[off]) = *(uint32_t*)&lv;
                }
            }
        }
    } else {
#pragma unroll
        for (int mt = 0; mt < 4; mt++) {
            const int gm = bm + wm * 64 + mt * 16 + (lane >> 2);
#pragma unroll
            for (int n8 = 0; n8 < 4; n8++) {
                const int gc = bn + wn * 32 + n8 * 8 + ((lane & 3) << 1);
                *(float2*)(&C[(size_t)gm * N + gc]) =
                    make_float2(acc[mt][n8][0], acc[mt][n8][1]);
                *(float2*)(&C[(size_t)(gm + 8) * N + gc]) =
                    make_float2(acc[mt][n8][2], acc[mt][n8][3]);
            }
        }
    }
}

// ---------------------------------------------------------------------------
// RoPE: reads fp32 g_q/g_k, writes bf16 hi/lo planes qh/ql/kh/kl.
// ---------------------------------------------------------------------------
__global__ __launch_bounds__(256) void rope_split()
{
    int idx = blockIdx.x * 256 + threadIdx.x;
    int i = idx & 63;
    int m = idx >> 10;
    int s = m & (CS - 1);

    float inv = g_invf[i];
    float ang = (float)s * inv;
    float c, sn;
    sincosf(ang, &sn, &c);

    int h = (idx >> 6) & (CH - 1);
    size_t base = (size_t)m * CD + (size_t)h * CHD;

    float q1 = g_q[base + i], q2 = g_q[base + i + 64];
    float rq1 = q1 * c - q2 * sn;
    float rq2 = q2 * c + q1 * sn;
    float k1 = g_k[base + i], k2 = g_k[base + i + 64];
    float rk1 = k1 * c - k2 * sn;
    float rk2 = k2 * c + k1 * sn;

    __nv_bfloat16 h1 = __float2bfloat16_rn(rq1);
    __nv_bfloat16 h2 = __float2bfloat16_rn(rq2);
    g_qh[base + i]      = h1;
    g_qh[base + i + 64] = h2;
    g_ql[base + i]      = __float2bfloat16_rn(rq1 - __bfloat162float(h1));
    g_ql[base + i + 64] = __float2bfloat16_rn(rq2 - __bfloat162float(h2));

    __nv_bfloat16 h3 = __float2bfloat16_rn(rk1);
    __nv_bfloat16 h4 = __float2bfloat16_rn(rk2);
    g_kh[base + i]      = h3;
    g_kh[base + i + 64] = h4;
    g_kl[base + i]      = __float2bfloat16_rn(rk1 - __bfloat162float(h3));
    g_kl[base + i + 64] = __float2bfloat16_rn(rk2 - __bfloat162float(h4));
}

// ---------------------------------------------------------------------------
// Flash attention, FA2-style, 2 CTAs/SM for cross-CTA phase overlap.
// CTA = 64 q-rows, 128 threads = 4 warps x 16 rows. Q fragments register-
// resident; softmax + P in registers. 64-col k-tiles, 2 fixed KV slots:
//   slot0 = K, slot1 = V.
// Schedule per iter t:
//   wait<0> (K(t) resident) -> sync -> issueV(t) -> QK(t) -> sync ->
//   issueK(t+1) -> softmax -> wait<1> (V(t) resident) -> sync -> PV(t)
// smem: Q 2x17408 + 2 slots x 34816 = 104448 B -> 2 CTAs/SM.
// ---------------------------------------------------------------------------
#define FOFF_QH  0
#define FOFF_QL  17408
#define FOFF_KV  34816
#define KVSLOT   34816          // 64 rows x 272B x 2 planes (h @0, l @17408)
#define FLASH_SMEM 104448

__global__ __launch_bounds__(128, 2) void flash_mma(const float* __restrict__ mask)
{
    extern __shared__ char smc[];

    const int tid  = threadIdx.x;
    const int lane = tid & 31;
    const int wid  = tid >> 5;      // 0..3: warp owns rows wid*16..wid*16+15
    const int b    = blockIdx.z;
    const int h    = blockIdx.y;
    const int q0   = blockIdx.x << 6;

    const __nv_bfloat16* Qhg = g_qh + (size_t)(b * CS + q0) * CD + (size_t)h * CHD;
    const __nv_bfloat16* Qlg = g_ql + (size_t)(b * CS + q0) * CD + (size_t)h * CHD;
    const __nv_bfloat16* Khg = g_kh + (size_t)(b * CS) * CD + (size_t)h * CHD;
    const __nv_bfloat16* Klg = g_kl + (size_t)(b * CS) * CD + (size_t)h * CHD;
    const __nv_bfloat16* Vhg = g_vh + (size_t)(b * CS) * CD + (size_t)h * CHD;
    const __nv_bfloat16* Vlg = g_vl + (size_t)(b * CS) * CD + (size_t)h * CHD;

    const uint32_t sQ_u  = smem_u32(smc) + FOFF_QH;
    const uint32_t kbuf  = smem_u32(smc) + FOFF_KV;            // slot0
    const uint32_t vbuf  = smem_u32(smc) + FOFF_KV + KVSLOT;   // slot1

    auto issueK = [&](int t) {
        if (t < 32) {
            const int k0 = t << 6;
            for (int i = tid; i < 1024; i += 128) {
                int r = i >> 4, c = i & 15;
                cp16(kbuf + r * 272 + c * 16,
                     Khg + (size_t)(k0 + r) * CD + c * 8);
                cp16(kbuf + 17408 + r * 272 + c * 16,
                     Klg + (size_t)(k0 + r) * CD + c * 8);
            }
        }
        cp_commit();
    };
    auto issueV = [&](int t) {
        if (t < 32) {
            const int k0 = t << 6;
            for (int i = tid; i < 1024; i += 128) {
                int r = i >> 4, c = i & 15;
                cp16(vbuf + r * 272 + c * 16,
                     Vhg + (size_t)(k0 + r) * CD + c * 8);
                cp16(vbuf + 17408 + r * 272 + c * 16,
                     Vlg + (size_t)(k0 + r) * CD + c * 8);
            }
        }
        cp_commit();
    };

    // prologue: Q group, then K0
    for (int i = tid; i < 1024; i += 128) {
        int r = i >> 4, c = i & 15;
        cp16(sQ_u + r * 272 + c * 16,         Qhg + (size_t)r * CD + c * 8);
        cp16(sQ_u + 17408 + r * 272 + c * 16, Qlg + (size_t)r * CD + c * 8);
    }
    cp_commit();
    issueK(0);

    // lane address components (proven formulas, warp tile = 16 rows)
    const int a_r   = wid * 16 + (lane & 15);
    const int a_c   = lane >> 4;
    const int b_r16 = (lane & 7) + ((lane >> 4) << 3);
    const int b_c   = (lane >> 3) & 1;
    const int v_key = ((lane >> 3) & 1) * 8 + (lane & 7);
    const int v_cg  = (lane >> 4) << 3;
    const int row0  = wid * 16 + (lane >> 2);
    const int colb  = (lane & 3) << 1;

    // hoist Q fragments (Q group drained; K0 may pend)
    cp_wait<1>();
    __syncthreads();
    uint32_t qh_f[8][4], ql_f[8][4];
#pragma unroll
    for (int tt = 0; tt < 8; tt++) {
        uint32_t addr = sQ_u + a_r * 272 + (tt * 2 + a_c) * 16;
        ldsm4(qh_f[tt][0], qh_f[tt][1], qh_f[tt][2], qh_f[tt][3], addr);
        ldsm4(ql_f[tt][0], ql_f[tt][1], ql_f[tt][2], ql_f[tt][3], addr + 17408);
    }

    // per-thread state: two rows (r0 = wid*16 + lane/4, r1 = r0 + 8)
    float m_pr0 = -INFINITY, m_pr1 = -INFINITY;
    float l_pr0 = 0.f,       l_pr1 = 0.f;
    float oacc[16][4];
#pragma unroll
    for (int i = 0; i < 16; i++)
#pragma unroll
        for (int r = 0; r < 4; r++) oacc[i][r] = 0.f;

    const float* mrow0 = mask + ((size_t)b * CS + (q0 + row0)) * CS;
    const float* mrow1 = mrow0 + (size_t)8 * CS;

    for (int t = 0; t < 32; t++) {
        const int k0 = t << 6;

        // K(t) resident; all warps past PV(t-1) (slot1 reads done)
        cp_wait<0>();
        __syncthreads();
        issueV(t);       // slot1, consumed later this iteration

        // prefetch mask values (hidden under QK MMA)
        float2 mr0[8], mr1[8];
#pragma unroll
        for (int n8 = 0; n8 < 8; n8++) {
            mr0[n8] = *(const float2*)(mrow0 + k0 + n8 * 8 + colb);
            mr1[n8] = *(const float2*)(mrow1 + k0 + n8 * 8 + colb);
        }

        // ---- S = Q K^T (bf16x3): warp computes 16 rows x 64 cols ----
        float sacc[8][4];
#pragma unroll
        for (int i = 0; i < 8; i++)
#pragma unroll
            for (int r = 0; r < 4; r++) sacc[i][r] = 0.f;

#pragma unroll
        for (int tt = 0; tt < 8; tt++) {
            uint32_t bh[8][2], bl[8][2];
#pragma unroll
            for (int g = 0; g < 4; g++) {
                uint32_t addr = kbuf + (g * 16 + b_r16) * 272 + (tt * 2 + b_c) * 16;
                ldsm4(bh[2*g][0], bh[2*g][1], bh[2*g+1][0], bh[2*g+1][1], addr);
                ldsm4(bl[2*g][0], bl[2*g][1], bl[2*g+1][0], bl[2*g+1][1], addr + 17408);
            }
#pragma unroll
            for (int n8 = 0; n8 < 8; n8++) {
                mma16816(sacc[n8], qh_f[tt], bh[n8]);
                mma16816(sacc[n8], qh_f[tt], bl[n8]);
                mma16816(sacc[n8], ql_f[tt], bh[n8]);
            }
        }
        __syncthreads();   // all warps done reading K(t) slot
        issueK(t + 1);     // slot0

        // ---- register softmax ----
        float mx0 = -INFINITY, mx1 = -INFINITY;
#pragma unroll
        for (int n8 = 0; n8 < 8; n8++) {
            sacc[n8][0] = sacc[n8][0] * SCALE + mr0[n8].x;
            sacc[n8][1] = sacc[n8][1] * SCALE + mr0[n8].y;
            sacc[n8][2] = sacc[n8][2] * SCALE + mr1[n8].x;
            sacc[n8][3] = sacc[n8][3] * SCALE + mr1[n8].y;
            mx0 = fmaxf(mx0, fmaxf(sacc[n8][0], sacc[n8][1]));
            mx1 = fmaxf(mx1, fmaxf(sacc[n8][2], sacc[n8][3]));
        }
        mx0 = fmaxf(mx0, __shfl_xor_sync(0xffffffffu, mx0, 1));
        mx0 = fmaxf(mx0, __shfl_xor_sync(0xffffffffu, mx0, 2));
        mx1 = fmaxf(mx1, __shfl_xor_sync(0xffffffffu, mx1, 1));
        mx1 = fmaxf(mx1, __shfl_xor_sync(0xffffffffu, mx1, 2));
        mx0 = fmaxf(mx0, m_pr0);
        mx1 = fmaxf(mx1, m_pr1);
        const float al0 = __expf(m_pr0 - mx0);
        const float al1 = __expf(m_pr1 - mx1);

        float sum0 = 0.f, sum1 = 0.f;
        uint32_t ph0[8], ph1[8], pl0[8], pl1[8];
#pragma unroll
        for (int n8 = 0; n8 < 8; n8++) {
            float p0 = __expf(sacc[n8][0] - mx0);
            float p1 = __expf(sacc[n8][1] - mx0);
            float p2 = __expf(sacc[n8][2] - mx1);
            float p3 = __expf(sacc[n8][3] - mx1);
            sum0 += p0 + p1;
            sum1 += p2 + p3;
            __nv_bfloat16 h0 = __float2bfloat16_rn(p0);
            __nv_bfloat16 h1 = __float2bfloat16_rn(p1);
            __nv_bfloat16 h2 = __float2bfloat16_rn(p2);
            __nv_bfloat16 h3 = __float2bfloat16_rn(p3);
            __nv_bfloat162 hv0(h0, h1), hv1(h2, h3);
            __nv_bfloat162 lv0(__float2bfloat16_rn(p0 - __bfloat162float(h0)),
                               __float2bfloat16_rn(p1 - __bfloat162float(h1)));
            __nv_bfloat162 lv1(__float2bfloat16_rn(p2 - __bfloat162float(h2)),
                               __float2bfloat16_rn(p3 - __bfloat162float(h3)));
            ph0[n8] = *(uint32_t*)&hv0;
            ph1[n8] = *(uint32_t*)&hv1;
            pl0[n8] = *(uint32_t*)&lv0;
            pl1[n8] = *(uint32_t*)&lv1;
        }
        sum0 += __shfl_xor_sync(0xffffffffu, sum0, 1);
        sum0 += __shfl_xor_sync(0xffffffffu, sum0, 2);
        sum1 += __shfl_xor_sync(0xffffffffu, sum1, 1);
        sum1 += __shfl_xor_sync(0xffffffffu, sum1, 2);
        l_pr0 = l_pr0 * al0 + sum0;
        l_pr1 = l_pr1 * al1 + sum1;
        m_pr0 = mx0;
        m_pr1 = mx1;

        // rescale output accumulator
#pragma unroll
        for (int n8 = 0; n8 < 16; n8++) {
            oacc[n8][0] *= al0;
            oacc[n8][1] *= al0;
            oacc[n8][2] *= al1;
            oacc[n8][3] *= al1;
        }

        cp_wait<1>();      // V(t) resident (K(t+1) in flight)
        __syncthreads();   // V(t) writes visible to all warps

        // ---- O += P V (bf16x3): A-frags straight from P registers ----
#pragma unroll
        for (int kt = 0; kt < 4; kt++) {
            uint32_t paH[4] = { ph0[2*kt], ph1[2*kt], ph0[2*kt+1], ph1[2*kt+1] };
            uint32_t paL[4] = { pl0[2*kt], pl1[2*kt], pl0[2*kt+1], pl1[2*kt+1] };
#pragma unroll
            for (int g = 0; g < 8; g++) {
                uint32_t vh[4], vl[4];
                uint32_t addr = vbuf + (kt * 16 + v_key) * 272 + (g * 16 + v_cg) * 2;
                ldsm4t(vh[0], vh[1], vh[2], vh[3], addr);
                ldsm4t(vl[0], vl[1], vl[2], vl[3], addr + 17408);
                uint32_t bH0[2] = { vh[0], vh[1] }, bL0[2] = { vl[0], vl[1] };
                uint32_t bH1[2] = { vh[2], vh[3] }, bL1[2] = { vl[2], vl[3] };
                mma16816(oacc[2*g],     paH, bH0);
                mma16816(oacc[2*g],     paH, bL0);
                mma16816(oacc[2*g],     paL, bH0);
                mma16816(oacc[2*g+1],   paH, bH1);
                mma16816(oacc[2*g+1],   paH, bL1);
                mma16816(oacc[2*g+1],   paL, bH1);
            }
        }
    }

    // epilogue: /l, bf16 hi/lo split store (rows row0, row0+8)
    const float inv0 = 1.0f / l_pr0;
    const float inv1 = 1.0f / l_pr1;
#pragma unroll
    for (int n8 = 0; n8 < 16; n8++) {
        const int cc = n8 * 8 + colb;
#pragma unroll
        for (int hrow = 0; hrow < 2; hrow++) {
            float o0 = oacc[n8][hrow * 2]     * (hrow ? inv1 : inv0);
            float o1 = oacc[n8][hrow * 2 + 1] * (hrow ? inv1 : inv0);
            size_t off = (size_t)(b * CS + q0 + row0 + hrow * 8) * CD
                       + (size_t)h * CHD + cc;
            __nv_bfloat16 h0 = __float2bfloat16_rn(o0);
            __nv_bfloat16 h1 = __float2bfloat16_rn(o1);
            __nv_bfloat162 hv(h0, h1);
            __nv_bfloat162 lv(__float2bfloat16_rn(o0 - __bfloat162float(h0)),
                              __float2bfloat16_rn(o1 - __bfloat162float(h1)));
            *(uint32_t*)(&g_aoh[off]) = *(uint32_t*)&hv;
            *(uint32_t*)(&g_aol[off]) = *(uint32_t*)&lv;
        }
    }
}

// ---------------------------------------------------------------------------
extern "C" void kernel_launch(void* const* d_in, const int* in_sizes, int n_in,
                              void* d_out, int out_size)
{
    const float* X    = (const float*)d_in[0];
    const float* mask = (const float*)d_in[1];
    const float* Wq   = (const float*)d_in[2];
    const float* Wk   = (const float*)d_in[3];
    const float* Wv   = (const float*)d_in[4];
    const float* Wo   = (const float*)d_in[5];
    float* out = (float*)d_out;

    float *qp, *kp;
    cudaGetSymbolAddress((void**)&qp, g_q);
    cudaGetSymbolAddress((void**)&kp, g_k);
    __nv_bfloat16 *xh, *xl, *wqh, *wql, *wkh, *wkl, *wvh, *wvl, *woh, *wol, *aoh, *aol;
    __nv_bfloat16 *vh, *vl;
    cudaGetSymbolAddress((void**)&xh,  g_xh);
    cudaGetSymbolAddress((void**)&xl,  g_xl);
    cudaGetSymbolAddress((void**)&wqh, g_wqh);
    cudaGetSymbolAddress((void**)&wql, g_wql);
    cudaGetSymbolAddress((void**)&wkh, g_wkh);
    cudaGetSymbolAddress((void**)&wkl, g_wkl);
    cudaGetSymbolAddress((void**)&wvh, g_wvh);
    cudaGetSymbolAddress((void**)&wvl, g_wvl);
    cudaGetSymbolAddress((void**)&woh, g_woh);
    cudaGetSymbolAddress((void**)&wol, g_wol);
    cudaGetSymbolAddress((void**)&aoh, g_aoh);
    cudaGetSymbolAddress((void**)&aol, g_aol);
    cudaGetSymbolAddress((void**)&vh,  g_vh);
    cudaGetSymbolAddress((void**)&vl,  g_vl);

    cudaFuncSetAttribute(flash_mma, cudaFuncAttributeMaxDynamicSharedMemorySize,
                         FLASH_SMEM);
    cudaFuncSetAttribute(gemm_bf16x3, cudaFuncAttributeMaxDynamicSharedMemorySize,
                         GEMM_SMEM);

    init_invf<<<1, 64>>>();

    const int n4x = CM * CD / 4, n4w = CD * CD / 4;
    convert_hilo<<<dim3(n4x / 256, 1), 256>>>(X, xh, xl, X, xh, xl, X, xh, xl,
                                              X, xh, xl, n4x);
    convert_hilo<<<dim3(n4w / 256, 4), 256>>>(Wq, wqh, wql, Wk, wkh, wkl,
                                              Wv, wvh, wvl, Wo, woh, wol, n4w);

    // fused Q/K/V projections; z==2 (V) writes bf16 hi/lo planes directly
    gemm_bf16x3<<<dim3(CD / 128, CM / 128, 3), 256, GEMM_SMEM>>>(
        xh, xl, wqh, wql, wkh, wkl, wvh, wvl, qp, kp, vh, vl, 2, CD, CD);

    rope_split<<<(CM * CH * 64) / 256, 256>>>();

    flash_mma<<<dim3(CS / 64, CH, CB), 128, FLASH_SMEM>>>(mask);

    // O projection (fp32 out)
    gemm_bf16x3<<<dim3(CD / 128, CM / 128, 1), 256, GEMM_SMEM>>>(
        aoh, aol, woh, wol, woh, wol, woh, wol, out, out, nullptr, nullptr, -1, CD, CD);
}